// round 1
// baseline (speedup 1.0000x reference)
#include <cuda_runtime.h>
#include <cstdint>
#include <cstddef>

// ---------------------------------------------------------------------------
// Merge_MixtralSparseMoeBlock — GB300 baseline
//
// Shapes: N=8192 tokens, H=2048, I=7168, E=8, R=398, K(top)=2.
// Reference normalizes top-k weights then sums them -> combine scale == 1.0
// exactly, so: out = expert(x), and router_logits = x @ gate_w^T is only
// needed as the second output.
//
// expert(x):
//   t1 = x@v1^T ; t3 = x@v3^T                       [N,R]
//   gate = x@w1^T + t1@u1^T ; up = x@w3^T + t3@u3^T [N,I]
//   h = silu(gate)*up                               [N,I]
//   t2 = h@v2^T ; out = h@w2^T + t2@u2^T            [N,H]
//
// One generic fp32 tile-GEMM (two K-phases to fold the low-rank delta),
// using packed fma.rn.f32x2 (Blackwell FFMA2, 2 FMA/lane/inst).
// ---------------------------------------------------------------------------

#define BM 128
#define BN 128
#define BK 16

static const int    NTOK = 8192;
static const int    HDIM = 2048;
static const int    IDIM = 7168;
static const int    RDIM = 398;
static const int    EDIM = 8;

// Scratch (device globals — no allocation allowed in this file)
__device__ float g_gate[(size_t)8192 * 7168];   // gate, then h in-place
__device__ float g_up  [(size_t)8192 * 7168];
__device__ float g_t1  [(size_t)8192 * 398];
__device__ float g_t3  [(size_t)8192 * 398];
__device__ float g_t2  [(size_t)8192 * 398];

// ---- packed f32x2 helpers --------------------------------------------------
__device__ __forceinline__ unsigned long long dup_f32(float a) {
    unsigned long long r;
    asm("mov.b64 %0, {%1, %1};" : "=l"(r) : "f"(a));
    return r;
}
__device__ __forceinline__ unsigned long long pack_f32(float lo, float hi) {
    unsigned long long r;
    asm("mov.b64 %0, {%1, %2};" : "=l"(r) : "f"(lo), "f"(hi));
    return r;
}
__device__ __forceinline__ void fma2(unsigned long long& d,
                                     unsigned long long a,
                                     unsigned long long b) {
    asm("fma.rn.f32x2 %0, %1, %2, %0;" : "+l"(d) : "l"(a), "l"(b));
}
__device__ __forceinline__ void unpack_f32(unsigned long long v, float& lo, float& hi) {
    asm("mov.b64 {%0, %1}, %2;" : "=f"(lo), "=f"(hi) : "l"(v));
}

// ---------------------------------------------------------------------------
// C[M,N] = A1[M,K1] @ B1[N,K1]^T + A2[M,K2] @ B2[N,K2]^T
// All row-major; leading dims = K1 / K2 / ldc. M must be a multiple of 128
// (always 8192 here). N and K arbitrary (guarded).
// 256 threads; thread (tm,tn) computes rows {tm*4..+3, 64+tm*4..+3} ×
// cols {tn*4..+3, 64+tn*4..+3}  (split-tile for conflict-free LDS).
// ---------------------------------------------------------------------------
__global__ __launch_bounds__(256, 2)
void sgemm2_kernel(const float* __restrict__ A1, const float* __restrict__ B1, int K1,
                   const float* __restrict__ A2, const float* __restrict__ B2, int K2,
                   float* __restrict__ C, int N, int ldc)
{
    __shared__ float As[BM][BK + 1];
    __shared__ float Bs[BN][BK + 1];

    const int t  = threadIdx.x;
    const int tn = t & 15;
    const int tm = t >> 4;
    const int m0 = blockIdx.y * BM;
    const int n0 = blockIdx.x * BN;

    unsigned long long acc[8][4];
#pragma unroll
    for (int r = 0; r < 8; r++)
#pragma unroll
        for (int p = 0; p < 4; p++) acc[r][p] = 0ull;

#pragma unroll 1
    for (int phase = 0; phase < 2; phase++) {
        const float* __restrict__ A = phase ? A2 : A1;
        const float* __restrict__ B = phase ? B2 : B1;
        const int K = phase ? K2 : K1;

#pragma unroll 1
        for (int k0 = 0; k0 < K; k0 += BK) {
            // Load A tile (128 x 16), k-fastest for coalescing
#pragma unroll
            for (int i = 0; i < 8; i++) {
                int idx = i * 256 + t;
                int k = idx & (BK - 1);
                int m = idx >> 4;
                int gk = k0 + k;
                float v = 0.f;
                if (gk < K) v = A[(size_t)(m0 + m) * K + gk];
                As[m][k] = v;
            }
            // Load B tile (128 x 16)
#pragma unroll
            for (int i = 0; i < 8; i++) {
                int idx = i * 256 + t;
                int k = idx & (BK - 1);
                int n = idx >> 4;
                int gk = k0 + k;
                int gn = n0 + n;
                float v = 0.f;
                if (gn < N && gk < K) v = B[(size_t)gn * K + gk];
                Bs[n][k] = v;
            }
            __syncthreads();

#pragma unroll
            for (int kk = 0; kk < BK; kk++) {
                unsigned long long ad[8], bp[4];
#pragma unroll
                for (int r = 0; r < 4; r++) {
                    ad[r]     = dup_f32(As[tm * 4 + r][kk]);
                    ad[4 + r] = dup_f32(As[64 + tm * 4 + r][kk]);
                }
                bp[0] = pack_f32(Bs[tn * 4 + 0][kk], Bs[tn * 4 + 1][kk]);
                bp[1] = pack_f32(Bs[tn * 4 + 2][kk], Bs[tn * 4 + 3][kk]);
                bp[2] = pack_f32(Bs[64 + tn * 4 + 0][kk], Bs[64 + tn * 4 + 1][kk]);
                bp[3] = pack_f32(Bs[64 + tn * 4 + 2][kk], Bs[64 + tn * 4 + 3][kk]);
#pragma unroll
                for (int r = 0; r < 8; r++)
#pragma unroll
                    for (int p = 0; p < 4; p++)
                        fma2(acc[r][p], ad[r], bp[p]);
            }
            __syncthreads();
        }
    }

    // Store
#pragma unroll
    for (int r = 0; r < 8; r++) {
        int gm = m0 + ((r < 4) ? (tm * 4 + r) : (64 + tm * 4 + (r - 4)));
#pragma unroll
        for (int p = 0; p < 4; p++) {
            int gn = n0 + ((p < 2) ? (tn * 4 + p * 2) : (64 + tn * 4 + (p - 2) * 2));
            float lo, hi;
            unpack_f32(acc[r][p], lo, hi);
            if (gn < N)     C[(size_t)gm * ldc + gn]     = lo;
            if (gn + 1 < N) C[(size_t)gm * ldc + gn + 1] = hi;
        }
    }
}

// h = silu(gate) * up, in-place into gate buffer. n divisible by 4.
__global__ void silu_mul_kernel(float* __restrict__ g, const float* __restrict__ u, size_t n4)
{
    size_t i = (size_t)blockIdx.x * blockDim.x + threadIdx.x;
    if (i >= n4) return;
    float4 gv = reinterpret_cast<const float4*>(g)[i];
    float4 uv = reinterpret_cast<const float4*>(u)[i];
    gv.x = gv.x / (1.f + expf(-gv.x)) * uv.x;
    gv.y = gv.y / (1.f + expf(-gv.y)) * uv.y;
    gv.z = gv.z / (1.f + expf(-gv.z)) * uv.z;
    gv.w = gv.w / (1.f + expf(-gv.w)) * uv.w;
    reinterpret_cast<float4*>(g)[i] = gv;
}

static inline dim3 grid_for(int M, int N) {
    return dim3((unsigned)((N + BN - 1) / BN), (unsigned)((M + BM - 1) / BM));
}

extern "C" void kernel_launch(void* const* d_in, const int* in_sizes, int n_in,
                              void* d_out, int out_size)
{
    const float* x  = (const float*)d_in[0];
    const float* gw = (const float*)d_in[1];
    const float* w1 = (const float*)d_in[2];
    const float* w2 = (const float*)d_in[3];
    const float* w3 = (const float*)d_in[4];
    const float* u1 = (const float*)d_in[5];
    const float* v1 = (const float*)d_in[6];
    const float* u2 = (const float*)d_in[7];
    const float* v2 = (const float*)d_in[8];
    const float* u3 = (const float*)d_in[9];
    const float* v3 = (const float*)d_in[10];

    float* out    = (float*)d_out;
    float* logits = out + (size_t)NTOK * HDIM;

    float *gate, *up, *t1, *t3, *t2;
    cudaGetSymbolAddress((void**)&gate, g_gate);
    cudaGetSymbolAddress((void**)&up,   g_up);
    cudaGetSymbolAddress((void**)&t1,   g_t1);
    cudaGetSymbolAddress((void**)&t3,   g_t3);
    cudaGetSymbolAddress((void**)&t2,   g_t2);

    dim3 blk(256);

    // t1 = x @ v1^T ; t3 = x @ v3^T
    sgemm2_kernel<<<grid_for(NTOK, RDIM), blk>>>(x, v1, HDIM, nullptr, nullptr, 0,
                                                 t1, RDIM, RDIM);
    sgemm2_kernel<<<grid_for(NTOK, RDIM), blk>>>(x, v3, HDIM, nullptr, nullptr, 0,
                                                 t3, RDIM, RDIM);
    // gate = x@w1^T + t1@u1^T ; up = x@w3^T + t3@u3^T
    sgemm2_kernel<<<grid_for(NTOK, IDIM), blk>>>(x, w1, HDIM, t1, u1, RDIM,
                                                 gate, IDIM, IDIM);
    sgemm2_kernel<<<grid_for(NTOK, IDIM), blk>>>(x, w3, HDIM, t3, u3, RDIM,
                                                 up, IDIM, IDIM);
    // h = silu(gate)*up  (in-place into gate)
    {
        size_t n4 = (size_t)NTOK * IDIM / 4;
        int tpb = 256;
        unsigned nb = (unsigned)((n4 + tpb - 1) / tpb);
        silu_mul_kernel<<<nb, tpb>>>(gate, up, n4);
    }
    // t2 = h @ v2^T
    sgemm2_kernel<<<grid_for(NTOK, RDIM), blk>>>(gate, v2, IDIM, nullptr, nullptr, 0,
                                                 t2, RDIM, RDIM);
    // out = h@w2^T + t2@u2^T
    sgemm2_kernel<<<grid_for(NTOK, HDIM), blk>>>(gate, w2, IDIM, t2, u2, RDIM,
                                                 out, HDIM, HDIM);
    // router_logits = x @ gate_w^T
    sgemm2_kernel<<<grid_for(NTOK, EDIM), blk>>>(x, gw, HDIM, nullptr, nullptr, 0,
                                                 logits, EDIM, EDIM);
}

// round 3
// speedup vs baseline: 2.9299x; 2.9299x over previous
#include <cuda_runtime.h>
#include <cuda_bf16.h>
#include <cstdint>
#include <cstddef>

// ---------------------------------------------------------------------------
// Merge_MixtralSparseMoeBlock — bf16-split mma.sync (sm_80-style, runs on the
// base sm_103 target the harness uses; tcgen05 is 'a'-gated and unavailable).
//
//   t1 = x@v1^T ; t3 = x@v3^T
//   gate = x@w1^T + t1@u1^T ; up = x@w3^T + t3@u3^T
//   h = silu(gate)*up
//   t2 = h@v2^T ; out = h@w2^T + t2@u2^T ; logits = x@gate_w^T
//
// fp32 -> (hi, lo) bf16 planes; each GEMM does 3 passes hi*hi + hi*lo + lo*hi
// accumulated in fp32 (drops only the ~2^-32 lo*lo term).
// ---------------------------------------------------------------------------

#define NTOK 8192
#define HDIM 2048
#define IDIM 7168
#define RDIM 398
#define RPAD 448        // multiple of 32/64, 16B-aligned rows

// ---------------- device scratch (no allocation allowed) -------------------
__device__ __align__(16) __nv_bfloat16 g_xs [2ull * NTOK * HDIM];
__device__ __align__(16) __nv_bfloat16 g_w1s[2ull * IDIM * HDIM];
__device__ __align__(16) __nv_bfloat16 g_w3s[2ull * IDIM * HDIM];
__device__ __align__(16) __nv_bfloat16 g_w2s[2ull * HDIM * IDIM];
__device__ __align__(16) __nv_bfloat16 g_v1s[2ull * RDIM * HDIM];
__device__ __align__(16) __nv_bfloat16 g_v3s[2ull * RDIM * HDIM];
__device__ __align__(16) __nv_bfloat16 g_v2s[2ull * RDIM * IDIM];
__device__ __align__(16) __nv_bfloat16 g_u1s[2ull * IDIM * RPAD];
__device__ __align__(16) __nv_bfloat16 g_u3s[2ull * IDIM * RPAD];
__device__ __align__(16) __nv_bfloat16 g_u2s[2ull * HDIM * RPAD];
__device__ __align__(16) __nv_bfloat16 g_hs [2ull * NTOK * IDIM];
__device__ __align__(16) __nv_bfloat16 g_t1s[2ull * NTOK * RPAD];
__device__ __align__(16) __nv_bfloat16 g_t3s[2ull * NTOK * RPAD];
__device__ __align__(16) __nv_bfloat16 g_t2s[2ull * NTOK * RPAD];
__device__ __align__(16) float g_gate[(size_t)NTOK * IDIM];
__device__ __align__(16) float g_up  [(size_t)NTOK * IDIM];
__device__ __align__(16) float g_t1  [(size_t)NTOK * RPAD];
__device__ __align__(16) float g_t3  [(size_t)NTOK * RPAD];
__device__ __align__(16) float g_t2  [(size_t)NTOK * RPAD];

// ---------------- PTX helpers ----------------------------------------------
__device__ __forceinline__ uint32_t smem_u32(const void* p) {
    uint32_t a;
    asm("{ .reg .u64 t; cvta.to.shared.u64 t, %1; cvt.u32.u64 %0, t; }"
        : "=r"(a) : "l"(p));
    return a;
}
__device__ __forceinline__ void ldsm_x4(uint32_t* r, uint32_t addr) {
    asm volatile("ldmatrix.sync.aligned.m8n8.x4.shared.b16 {%0,%1,%2,%3}, [%4];"
                 : "=r"(r[0]), "=r"(r[1]), "=r"(r[2]), "=r"(r[3]) : "r"(addr));
}
__device__ __forceinline__ void mma_bf16(float* d, const uint32_t* a, const uint32_t* b) {
    asm volatile("mma.sync.aligned.m16n8k16.row.col.f32.bf16.bf16.f32 "
                 "{%0,%1,%2,%3}, {%4,%5,%6,%7}, {%8,%9}, {%0,%1,%2,%3};"
                 : "+f"(d[0]), "+f"(d[1]), "+f"(d[2]), "+f"(d[3])
                 : "r"(a[0]), "r"(a[1]), "r"(a[2]), "r"(a[3]),
                   "r"(b[0]), "r"(b[1]));
}
#define CP_COMMIT() asm volatile("cp.async.commit_group;" ::: "memory")
#define CP_WAIT1()  asm volatile("cp.async.wait_group 1;" ::: "memory")

// swizzle: rows are 64B (4 x 16B chunks); quad = (r*4 + c^((r>>1)&3)) % 8
// is distinct across any 8 consecutive rows -> conflict-free ldmatrix phases.
__device__ __forceinline__ uint32_t swz(int r, int c) {
    return (uint32_t)(r * 64 + ((c ^ ((r >> 1) & 3)) << 4));
}

// ---------------------------------------------------------------------------
#define BM 128
#define BN 128
#define BK 32
#define STAGES 3
#define PLANE_BYTES  8192                      // 128 x 32 bf16
#define STAGE_BYTES  (4 * PLANE_BYTES)         // Ah, Al, Bh, Bl
#define SMEM_TOTAL   (STAGES * STAGE_BYTES)    // 96 KB

// 128x32 bf16 tile -> swizzled smem, 2 cp.async(16B) per thread per plane.
__device__ __forceinline__ void load_plane(const __nv_bfloat16* __restrict__ g,
                                           int ld, int row0, int rowsValid,
                                           int k0, uint32_t sbase, int t) {
#pragma unroll
    for (int i = 0; i < 2; i++) {
        int idx = i * 256 + t;
        int r = idx >> 2;          // 0..127
        int c = idx & 3;           // 16B chunk
        int gr = row0 + r;
        bool ok = (gr < rowsValid);
        const void* gp = ok ? (const void*)(g + (size_t)gr * ld + k0 + c * 8)
                            : (const void*)g;
        uint32_t sp = sbase + swz(r, c);
        int sz = ok ? 16 : 0;
        asm volatile("cp.async.cg.shared.global [%0], [%1], 16, %2;"
                     :: "r"(sp), "l"(gp), "r"(sz));
    }
}

// C[M,N] = (A1h+A1l)(B1h+B1l)^T + (A2h+A2l)(B2h+B2l)^T  (3-pass bf16 split)
__global__ __launch_bounds__(256, 1)
void mmagemm(const __nv_bfloat16* __restrict__ A1, long long planeA1, int lda1, int K1,
             const __nv_bfloat16* __restrict__ B1, long long planeB1, int ldb1,
             const __nv_bfloat16* __restrict__ A2, long long planeA2, int lda2, int K2,
             const __nv_bfloat16* __restrict__ B2, long long planeB2, int ldb2,
             float* __restrict__ C, int N, int ldc)
{
    extern __shared__ char smem[];
    const int t    = threadIdx.x;
    const int lane = t & 31;
    const int wid  = t >> 5;
    const int wm   = wid & 3;            // 4 warps on M (32 rows each)
    const int wn   = wid >> 2;           // 2 warps on N (64 cols each)
    const int m0   = blockIdx.y * BM;
    const int n0   = blockIdx.x * BN;
    const uint32_t sb0 = smem_u32(smem);

    const int c1 = K1 >> 5;
    const int c2 = K2 >> 5;
    const int CT = c1 + c2;

    float acc[2][8][4];
#pragma unroll
    for (int i = 0; i < 2; i++)
#pragma unroll
        for (int j = 0; j < 8; j++)
#pragma unroll
            for (int k = 0; k < 4; k++) acc[i][j][k] = 0.f;

    // Precompute ldmatrix smem offsets (within a plane) per (tile, kstep).
    uint32_t aoff[2][2], boff[4][2];
#pragma unroll
    for (int mt = 0; mt < 2; mt++)
#pragma unroll
        for (int ks = 0; ks < 2; ks++) {
            int r = wm * 32 + mt * 16 + (lane & 15);
            int c = ks * 2 + (lane >> 4);
            aoff[mt][ks] = swz(r, c);
        }
#pragma unroll
    for (int nq = 0; nq < 4; nq++)
#pragma unroll
        for (int ks = 0; ks < 2; ks++) {
            int g  = lane >> 3;
            int nr = wn * 64 + nq * 16 + (lane & 7) + ((g & 2) << 2);
            int c  = ks * 2 + (g & 1);
            boff[nq][ks] = swz(nr, c);
        }

    auto issue = [&](int cc, int stage) {
        const __nv_bfloat16* A; const __nv_bfloat16* B;
        long long pA, pB; int lda, ldb, k0;
        if (cc < c1) { A = A1; B = B1; pA = planeA1; pB = planeB1;
                       lda = lda1; ldb = ldb1; k0 = cc * BK; }
        else         { A = A2; B = B2; pA = planeA2; pB = planeB2;
                       lda = lda2; ldb = ldb2; k0 = (cc - c1) * BK; }
        uint32_t sb = sb0 + stage * STAGE_BYTES;
        load_plane(A,      lda, m0, 1 << 30, k0, sb,                   t);
        load_plane(A + pA, lda, m0, 1 << 30, k0, sb + PLANE_BYTES,     t);
        load_plane(B,      ldb, n0, N,       k0, sb + 2 * PLANE_BYTES, t);
        load_plane(B + pB, ldb, n0, N,       k0, sb + 3 * PLANE_BYTES, t);
    };

    // prologue: 2 stages in flight
    issue(0, 0); CP_COMMIT();
    if (CT > 1) issue(1, 1);
    CP_COMMIT();

#pragma unroll 1
    for (int cc = 0; cc < CT; cc++) {
        CP_WAIT1();
        __syncthreads();

        const uint32_t sb = sb0 + (cc % STAGES) * STAGE_BYTES;
        const uint32_t sAh = sb, sAl = sb + PLANE_BYTES;
        const uint32_t sBh = sb + 2 * PLANE_BYTES, sBl = sb + 3 * PLANE_BYTES;

#pragma unroll
        for (int ks = 0; ks < 2; ks++) {
            uint32_t ah[2][4], al[2][4], bh[8][2], bl[8][2];
#pragma unroll
            for (int mt = 0; mt < 2; mt++) {
                ldsm_x4(ah[mt], sAh + aoff[mt][ks]);
                ldsm_x4(al[mt], sAl + aoff[mt][ks]);
            }
#pragma unroll
            for (int nq = 0; nq < 4; nq++) {
                uint32_t r[4];
                ldsm_x4(r, sBh + boff[nq][ks]);
                bh[nq * 2][0] = r[0]; bh[nq * 2][1] = r[1];
                bh[nq * 2 + 1][0] = r[2]; bh[nq * 2 + 1][1] = r[3];
                ldsm_x4(r, sBl + boff[nq][ks]);
                bl[nq * 2][0] = r[0]; bl[nq * 2][1] = r[1];
                bl[nq * 2 + 1][0] = r[2]; bl[nq * 2 + 1][1] = r[3];
            }
            // pass-outer order: 16 different accumulators between reuses
#pragma unroll
            for (int mt = 0; mt < 2; mt++)
#pragma unroll
                for (int nt = 0; nt < 8; nt++) mma_bf16(acc[mt][nt], ah[mt], bh[nt]);
#pragma unroll
            for (int mt = 0; mt < 2; mt++)
#pragma unroll
                for (int nt = 0; nt < 8; nt++) mma_bf16(acc[mt][nt], ah[mt], bl[nt]);
#pragma unroll
            for (int mt = 0; mt < 2; mt++)
#pragma unroll
                for (int nt = 0; nt < 8; nt++) mma_bf16(acc[mt][nt], al[mt], bh[nt]);
        }
        __syncthreads();

        int nc = cc + STAGES - 1;
        if (nc < CT) issue(nc, nc % STAGES);
        CP_COMMIT();
    }

    // Epilogue: direct fp32 stores
#pragma unroll
    for (int mt = 0; mt < 2; mt++) {
        int row = m0 + wm * 32 + mt * 16 + (lane >> 2);
#pragma unroll
        for (int nt = 0; nt < 8; nt++) {
            int col = n0 + wn * 64 + nt * 8 + (lane & 3) * 2;
            if (col < N) {
                float2 v0 = make_float2(acc[mt][nt][0], acc[mt][nt][1]);
                float2 v1 = make_float2(acc[mt][nt][2], acc[mt][nt][3]);
                *reinterpret_cast<float2*>(C + (size_t)row * ldc + col) = v0;
                *reinterpret_cast<float2*>(C + (size_t)(row + 8) * ldc + col) = v1;
            }
        }
    }
}

// ---------------------------------------------------------------------------
// fp32 -> bf16 (hi, lo) split with K padding.
__global__ void split_kernel(const float* __restrict__ src, int src_ld,
                             long long total, int cols, int dstK,
                             __nv_bfloat16* __restrict__ dst, long long plane)
{
    long long i = (long long)blockIdx.x * blockDim.x + threadIdx.x;
    if (i >= total) return;
    int k = (int)(i % dstK);
    long long r = i / dstK;
    float v = (k < cols) ? src[r * src_ld + k] : 0.f;
    __nv_bfloat16 hi = __float2bfloat16(v);
    __nv_bfloat16 lo = __float2bfloat16(v - __bfloat162float(hi));
    dst[i] = hi;
    dst[i + plane] = lo;
}

__global__ void silu_split_kernel(const float* __restrict__ g,
                                  const float* __restrict__ u,
                                  __nv_bfloat16* __restrict__ dst,
                                  long long n, long long plane)
{
    long long i = (long long)blockIdx.x * blockDim.x + threadIdx.x;
    if (i >= n) return;
    float gv = g[i];
    float h = gv / (1.f + expf(-gv)) * u[i];
    __nv_bfloat16 hi = __float2bfloat16(h);
    __nv_bfloat16 lo = __float2bfloat16(h - __bfloat162float(hi));
    dst[i] = hi;
    dst[i + plane] = lo;
}

__global__ void logits_kernel(const float* __restrict__ x,
                              const float* __restrict__ gw,
                              float* __restrict__ out)
{
    int warp = (blockIdx.x * blockDim.x + threadIdx.x) >> 5;
    int lane = threadIdx.x & 31;
    if (warp >= NTOK) return;
    const float* xr = x + (size_t)warp * HDIM;
    float acc[8] = {0.f, 0.f, 0.f, 0.f, 0.f, 0.f, 0.f, 0.f};
    for (int k = lane; k < HDIM; k += 32) {
        float xv = xr[k];
#pragma unroll
        for (int e = 0; e < 8; e++) acc[e] += xv * gw[e * HDIM + k];
    }
#pragma unroll
    for (int e = 0; e < 8; e++) {
        float v = acc[e];
#pragma unroll
        for (int o = 16; o; o >>= 1) v += __shfl_xor_sync(0xFFFFFFFFu, v, o);
        if (lane == 0) out[(size_t)warp * 8 + e] = v;
    }
}

// ---------------------------------------------------------------------------
static inline void run_split(const float* src, int src_ld, long long rows,
                             int cols, int dstK, __nv_bfloat16* dst)
{
    long long total = rows * dstK;
    int tpb = 256;
    unsigned nb = (unsigned)((total + tpb - 1) / tpb);
    split_kernel<<<nb, tpb>>>(src, src_ld, total, cols, dstK, dst, total);
}

extern "C" void kernel_launch(void* const* d_in, const int* in_sizes, int n_in,
                              void* d_out, int out_size)
{
    const float* x  = (const float*)d_in[0];
    const float* gw = (const float*)d_in[1];
    const float* w1 = (const float*)d_in[2];
    const float* w2 = (const float*)d_in[3];
    const float* w3 = (const float*)d_in[4];
    const float* u1 = (const float*)d_in[5];
    const float* v1 = (const float*)d_in[6];
    const float* u2 = (const float*)d_in[7];
    const float* v2 = (const float*)d_in[8];
    const float* u3 = (const float*)d_in[9];
    const float* v3 = (const float*)d_in[10];

    float* out    = (float*)d_out;
    float* logits = out + (size_t)NTOK * HDIM;

    __nv_bfloat16 *xs, *w1s, *w3s, *w2s, *v1s, *v3s, *v2s, *u1s, *u3s, *u2s;
    __nv_bfloat16 *hs, *t1s, *t3s, *t2s;
    float *gate, *up, *t1, *t3, *t2;
    cudaGetSymbolAddress((void**)&xs,  g_xs);
    cudaGetSymbolAddress((void**)&w1s, g_w1s);
    cudaGetSymbolAddress((void**)&w3s, g_w3s);
    cudaGetSymbolAddress((void**)&w2s, g_w2s);
    cudaGetSymbolAddress((void**)&v1s, g_v1s);
    cudaGetSymbolAddress((void**)&v3s, g_v3s);
    cudaGetSymbolAddress((void**)&v2s, g_v2s);
    cudaGetSymbolAddress((void**)&u1s, g_u1s);
    cudaGetSymbolAddress((void**)&u3s, g_u3s);
    cudaGetSymbolAddress((void**)&u2s, g_u2s);
    cudaGetSymbolAddress((void**)&hs,  g_hs);
    cudaGetSymbolAddress((void**)&t1s, g_t1s);
    cudaGetSymbolAddress((void**)&t3s, g_t3s);
    cudaGetSymbolAddress((void**)&t2s, g_t2s);
    cudaGetSymbolAddress((void**)&gate, g_gate);
    cudaGetSymbolAddress((void**)&up,   g_up);
    cudaGetSymbolAddress((void**)&t1,   g_t1);
    cudaGetSymbolAddress((void**)&t3,   g_t3);
    cudaGetSymbolAddress((void**)&t2,   g_t2);

    cudaFuncSetAttribute(mmagemm, cudaFuncAttributeMaxDynamicSharedMemorySize,
                         SMEM_TOTAL);

    // ---- splits of inputs --------------------------------------------------
    run_split(x,  HDIM, NTOK, HDIM, HDIM, xs);
    run_split(w1, HDIM, IDIM, HDIM, HDIM, w1s);
    run_split(w3, HDIM, IDIM, HDIM, HDIM, w3s);
    run_split(w2, IDIM, HDIM, IDIM, IDIM, w2s);
    run_split(v1, HDIM, RDIM, HDIM, HDIM, v1s);
    run_split(v3, HDIM, RDIM, HDIM, HDIM, v3s);
    run_split(v2, IDIM, RDIM, IDIM, IDIM, v2s);
    run_split(u1, RDIM, IDIM, RDIM, RPAD, u1s);
    run_split(u3, RDIM, IDIM, RDIM, RPAD, u3s);
    run_split(u2, RDIM, HDIM, RDIM, RPAD, u2s);

    const long long pX  = (long long)NTOK * HDIM;
    const long long pW1 = (long long)IDIM * HDIM;
    const long long pW2 = (long long)HDIM * IDIM;
    const long long pV1 = (long long)RDIM * HDIM;
    const long long pV2 = (long long)RDIM * IDIM;
    const long long pU1 = (long long)IDIM * RPAD;
    const long long pU2 = (long long)HDIM * RPAD;
    const long long pH  = (long long)NTOK * IDIM;
    const long long pT  = (long long)NTOK * RPAD;

    dim3 blk(256);
    dim3 gR((RDIM + BN - 1) / BN, NTOK / BM);   // (4, 64)
    dim3 gI(IDIM / BN, NTOK / BM);              // (56, 64)
    dim3 gH(HDIM / BN, NTOK / BM);              // (16, 64)

    // t1 = x@v1^T ; t3 = x@v3^T
    mmagemm<<<gR, blk, SMEM_TOTAL>>>(xs, pX, HDIM, HDIM, v1s, pV1, HDIM,
                                     nullptr, 0, 0, 0, nullptr, 0, 0,
                                     t1, RDIM, RPAD);
    mmagemm<<<gR, blk, SMEM_TOTAL>>>(xs, pX, HDIM, HDIM, v3s, pV1, HDIM,
                                     nullptr, 0, 0, 0, nullptr, 0, 0,
                                     t3, RDIM, RPAD);
    run_split(t1, RPAD, NTOK, RDIM, RPAD, t1s);
    run_split(t3, RPAD, NTOK, RDIM, RPAD, t3s);

    // gate = x@w1^T + t1@u1^T ; up = x@w3^T + t3@u3^T
    mmagemm<<<gI, blk, SMEM_TOTAL>>>(xs, pX, HDIM, HDIM, w1s, pW1, HDIM,
                                     t1s, pT, RPAD, RPAD, u1s, pU1, RPAD,
                                     gate, IDIM, IDIM);
    mmagemm<<<gI, blk, SMEM_TOTAL>>>(xs, pX, HDIM, HDIM, w3s, pW1, HDIM,
                                     t3s, pT, RPAD, RPAD, u3s, pU1, RPAD,
                                     up, IDIM, IDIM);

    // h = silu(gate)*up -> bf16 split planes
    {
        long long n = (long long)NTOK * IDIM;
        int tpb = 256;
        unsigned nb = (unsigned)((n + tpb - 1) / tpb);
        silu_split_kernel<<<nb, tpb>>>(gate, up, hs, n, pH);
    }

    // t2 = h@v2^T
    mmagemm<<<gR, blk, SMEM_TOTAL>>>(hs, pH, IDIM, IDIM, v2s, pV2, IDIM,
                                     nullptr, 0, 0, 0, nullptr, 0, 0,
                                     t2, RDIM, RPAD);
    run_split(t2, RPAD, NTOK, RDIM, RPAD, t2s);

    // out = h@w2^T + t2@u2^T
    mmagemm<<<gH, blk, SMEM_TOTAL>>>(hs, pH, IDIM, IDIM, w2s, pW2, IDIM,
                                     t2s, pT, RPAD, RPAD, u2s, pU2, RPAD,
                                     out, HDIM, HDIM);

    // router logits
    {
        int tpb = 256;
        unsigned nb = (unsigned)((NTOK * 32 + tpb - 1) / tpb);
        logits_kernel<<<nb, tpb>>>(x, gw, logits);
    }
}

// round 4
// speedup vs baseline: 3.6959x; 1.2614x over previous
#include <cuda_runtime.h>
#include <cuda_bf16.h>
#include <cstdint>
#include <cstddef>

// ---------------------------------------------------------------------------
// Merge_MixtralSparseMoeBlock — bf16-split mma.sync, BK=64 pipeline,
// fused epilogues (silu + hi/lo split) to kill intermediate traffic.
//
//   t1 = x@v1^T ; t3 = x@v3^T              (epilogue -> bf16 split planes)
//   gate = x@w1^T + t1@u1^T                (fp32)
//   up   = x@w3^T + t3@u3^T  -> epilogue: h = silu(gate)*up -> split planes
//   t2 = h@v2^T                            (epilogue -> split planes)
//   out = h@w2^T + t2@u2^T                 (fp32 -> d_out)
//   logits = x@gate_w^T
// ---------------------------------------------------------------------------

#define NTOK 8192
#define HDIM 2048
#define IDIM 7168
#define RDIM 398
#define RPAD 448

// ---------------- device scratch -------------------------------------------
__device__ __align__(16) __nv_bfloat16 g_xs [2ull * NTOK * HDIM];
__device__ __align__(16) __nv_bfloat16 g_w1s[2ull * IDIM * HDIM];
__device__ __align__(16) __nv_bfloat16 g_w3s[2ull * IDIM * HDIM];
__device__ __align__(16) __nv_bfloat16 g_w2s[2ull * HDIM * IDIM];
__device__ __align__(16) __nv_bfloat16 g_v1s[2ull * RDIM * HDIM];
__device__ __align__(16) __nv_bfloat16 g_v3s[2ull * RDIM * HDIM];
__device__ __align__(16) __nv_bfloat16 g_v2s[2ull * RDIM * IDIM];
__device__ __align__(16) __nv_bfloat16 g_u1s[2ull * IDIM * RPAD];
__device__ __align__(16) __nv_bfloat16 g_u3s[2ull * IDIM * RPAD];
__device__ __align__(16) __nv_bfloat16 g_u2s[2ull * HDIM * RPAD];
__device__ __align__(16) __nv_bfloat16 g_hs [2ull * NTOK * IDIM];
__device__ __align__(16) __nv_bfloat16 g_t1s[2ull * NTOK * RPAD];
__device__ __align__(16) __nv_bfloat16 g_t3s[2ull * NTOK * RPAD];
__device__ __align__(16) __nv_bfloat16 g_t2s[2ull * NTOK * RPAD];
__device__ __align__(16) float g_gate[(size_t)NTOK * IDIM];

// ---------------- PTX helpers ----------------------------------------------
__device__ __forceinline__ uint32_t smem_u32(const void* p) {
    uint32_t a;
    asm("{ .reg .u64 t; cvta.to.shared.u64 t, %1; cvt.u32.u64 %0, t; }"
        : "=r"(a) : "l"(p));
    return a;
}
__device__ __forceinline__ void ldsm_x4(uint32_t* r, uint32_t addr) {
    asm volatile("ldmatrix.sync.aligned.m8n8.x4.shared.b16 {%0,%1,%2,%3}, [%4];"
                 : "=r"(r[0]), "=r"(r[1]), "=r"(r[2]), "=r"(r[3]) : "r"(addr));
}
__device__ __forceinline__ void mma_bf16(float* d, const uint32_t* a, const uint32_t* b) {
    asm volatile("mma.sync.aligned.m16n8k16.row.col.f32.bf16.bf16.f32 "
                 "{%0,%1,%2,%3}, {%4,%5,%6,%7}, {%8,%9}, {%0,%1,%2,%3};"
                 : "+f"(d[0]), "+f"(d[1]), "+f"(d[2]), "+f"(d[3])
                 : "r"(a[0]), "r"(a[1]), "r"(a[2]), "r"(a[3]),
                   "r"(b[0]), "r"(b[1]));
}
#define CP_COMMIT() asm volatile("cp.async.commit_group;" ::: "memory")
#define CP_WAIT1()  asm volatile("cp.async.wait_group 1;" ::: "memory")

// BK=64: rows are 128B (8 x 16B chunks). chunk' = c ^ (r&7): conflict-free
// for both cp.async stores (c fastest) and ldmatrix phases (8 rows/phase).
__device__ __forceinline__ uint32_t swz(int r, int c) {
    return (uint32_t)(r * 128 + ((c ^ (r & 7)) << 4));
}

#define BM 128
#define BN 128
#define BK 64
#define STAGES 3
#define PLANE_BYTES  16384                     // 128 x 64 bf16
#define STAGE_BYTES  (4 * PLANE_BYTES)         // Ah, Al, Bh, Bl = 64 KB
#define SMEM_TOTAL   (STAGES * STAGE_BYTES)    // 192 KB

__device__ __forceinline__ void load_plane(const __nv_bfloat16* __restrict__ g,
                                           int ld, int row0, int rowsValid,
                                           int k0, uint32_t sbase, int t) {
#pragma unroll
    for (int i = 0; i < 4; i++) {
        int idx = i * 256 + t;
        int r = idx >> 3;          // 0..127
        int c = idx & 7;           // 16B chunk
        int gr = row0 + r;
        bool ok = (gr < rowsValid);
        const void* gp = ok ? (const void*)(g + (size_t)gr * ld + k0 + c * 8)
                            : (const void*)g;
        uint32_t sp = sbase + swz(r, c);
        int sz = ok ? 16 : 0;
        asm volatile("cp.async.cg.shared.global [%0], [%1], 16, %2;"
                     :: "r"(sp), "l"(gp), "r"(sz));
    }
}

__device__ __forceinline__ float siluf(float x) {
    return x / (1.f + __expf(-x));
}
__device__ __forceinline__ void split_store(__nv_bfloat16* Cs, long long plane,
                                            int ldcs, int row, int col,
                                            float v0, float v1) {
    __nv_bfloat16 h0 = __float2bfloat16(v0), h1 = __float2bfloat16(v1);
    __nv_bfloat16 l0 = __float2bfloat16(v0 - __bfloat162float(h0));
    __nv_bfloat16 l1 = __float2bfloat16(v1 - __bfloat162float(h1));
    size_t off = (size_t)row * ldcs + col;
    *reinterpret_cast<__nv_bfloat162*>(Cs + off)         = __halves2bfloat162(h0, h1);
    *reinterpret_cast<__nv_bfloat162*>(Cs + off + plane) = __halves2bfloat162(l0, l1);
}

// MODE: 0 = fp32 C out; 1 = bf16 split planes out; 2 = h=silu(C)*acc -> planes
template <int MODE>
__global__ __launch_bounds__(256, 1)
void mmagemm(const __nv_bfloat16* __restrict__ A1, long long planeA1, int lda1, int K1,
             const __nv_bfloat16* __restrict__ B1, long long planeB1, int ldb1,
             const __nv_bfloat16* __restrict__ A2, long long planeA2, int lda2, int K2,
             const __nv_bfloat16* __restrict__ B2, long long planeB2, int ldb2,
             float* __restrict__ C, int N, int ldc,
             __nv_bfloat16* __restrict__ Cs, long long planeCs, int ldcs)
{
    extern __shared__ char smem[];
    const int t    = threadIdx.x;
    const int lane = t & 31;
    const int wid  = t >> 5;
    const int wm   = wid & 3;
    const int wn   = wid >> 2;
    const int m0   = blockIdx.y * BM;
    const int n0   = blockIdx.x * BN;
    const uint32_t sb0 = smem_u32(smem);

    const int c1 = K1 >> 6;
    const int c2 = K2 >> 6;
    const int CT = c1 + c2;

    float acc[2][8][4];
#pragma unroll
    for (int i = 0; i < 2; i++)
#pragma unroll
        for (int j = 0; j < 8; j++)
#pragma unroll
            for (int k = 0; k < 4; k++) acc[i][j][k] = 0.f;

    // fragment address components
    int arow[2], amask[2]; uint32_t aoffr[2];
#pragma unroll
    for (int mt = 0; mt < 2; mt++) {
        arow[mt]  = wm * 32 + mt * 16 + (lane & 15);
        aoffr[mt] = (uint32_t)arow[mt] * 128;
        amask[mt] = arow[mt] & 7;
    }
    const int alo = lane >> 4;
    const int gq  = lane >> 3;
    int bmask[4]; uint32_t boffr[4];
#pragma unroll
    for (int nq = 0; nq < 4; nq++) {
        int nr = wn * 64 + nq * 16 + (lane & 7) + ((gq & 2) << 2);
        boffr[nq] = (uint32_t)nr * 128;
        bmask[nq] = nr & 7;
    }
    const int blo = gq & 1;

    auto issue = [&](int cc, int stage) {
        const __nv_bfloat16* A; const __nv_bfloat16* B;
        long long pA, pB; int lda, ldb, k0;
        if (cc < c1) { A = A1; B = B1; pA = planeA1; pB = planeB1;
                       lda = lda1; ldb = ldb1; k0 = cc * BK; }
        else         { A = A2; B = B2; pA = planeA2; pB = planeB2;
                       lda = lda2; ldb = ldb2; k0 = (cc - c1) * BK; }
        uint32_t sb = sb0 + stage * STAGE_BYTES;
        load_plane(A,      lda, m0, 1 << 30, k0, sb,                   t);
        load_plane(A + pA, lda, m0, 1 << 30, k0, sb + PLANE_BYTES,     t);
        load_plane(B,      ldb, n0, N,       k0, sb + 2 * PLANE_BYTES, t);
        load_plane(B + pB, ldb, n0, N,       k0, sb + 3 * PLANE_BYTES, t);
    };

    issue(0, 0); CP_COMMIT();
    if (CT > 1) issue(1, 1);
    CP_COMMIT();

#pragma unroll 1
    for (int cc = 0; cc < CT; cc++) {
        CP_WAIT1();
        __syncthreads();

        const uint32_t sb = sb0 + (cc % STAGES) * STAGE_BYTES;
        const uint32_t sAh = sb, sAl = sb + PLANE_BYTES;
        const uint32_t sBh = sb + 2 * PLANE_BYTES, sBl = sb + 3 * PLANE_BYTES;

#pragma unroll
        for (int ks = 0; ks < 4; ks++) {
            uint32_t ah[2][4], al[2][4], bh[8][2], bl[8][2];
            const int ac = ks * 2 + alo;
            const int bc = ks * 2 + blo;
#pragma unroll
            for (int mt = 0; mt < 2; mt++) {
                uint32_t ao = aoffr[mt] + (uint32_t)((ac ^ amask[mt]) << 4);
                ldsm_x4(ah[mt], sAh + ao);
                ldsm_x4(al[mt], sAl + ao);
            }
#pragma unroll
            for (int nq = 0; nq < 4; nq++) {
                uint32_t bo = boffr[nq] + (uint32_t)((bc ^ bmask[nq]) << 4);
                uint32_t r[4];
                ldsm_x4(r, sBh + bo);
                bh[nq * 2][0] = r[0]; bh[nq * 2][1] = r[1];
                bh[nq * 2 + 1][0] = r[2]; bh[nq * 2 + 1][1] = r[3];
                ldsm_x4(r, sBl + bo);
                bl[nq * 2][0] = r[0]; bl[nq * 2][1] = r[1];
                bl[nq * 2 + 1][0] = r[2]; bl[nq * 2 + 1][1] = r[3];
            }
#pragma unroll
            for (int mt = 0; mt < 2; mt++)
#pragma unroll
                for (int nt = 0; nt < 8; nt++) mma_bf16(acc[mt][nt], ah[mt], bh[nt]);
#pragma unroll
            for (int mt = 0; mt < 2; mt++)
#pragma unroll
                for (int nt = 0; nt < 8; nt++) mma_bf16(acc[mt][nt], ah[mt], bl[nt]);
#pragma unroll
            for (int mt = 0; mt < 2; mt++)
#pragma unroll
                for (int nt = 0; nt < 8; nt++) mma_bf16(acc[mt][nt], al[mt], bh[nt]);
        }
        __syncthreads();

        int nc = cc + STAGES - 1;
        if (nc < CT) issue(nc, nc % STAGES);
        CP_COMMIT();
    }

    // ---- epilogue ----
#pragma unroll
    for (int mt = 0; mt < 2; mt++) {
        int row = m0 + wm * 32 + mt * 16 + (lane >> 2);
#pragma unroll
        for (int nt = 0; nt < 8; nt++) {
            int col = n0 + wn * 64 + nt * 8 + (lane & 3) * 2;
            if (MODE == 0) {
                if (col < N) {
                    *reinterpret_cast<float2*>(C + (size_t)row * ldc + col) =
                        make_float2(acc[mt][nt][0], acc[mt][nt][1]);
                    *reinterpret_cast<float2*>(C + (size_t)(row + 8) * ldc + col) =
                        make_float2(acc[mt][nt][2], acc[mt][nt][3]);
                }
            } else if (MODE == 1) {
                if (col < ldcs) {
                    split_store(Cs, planeCs, ldcs, row, col,
                                acc[mt][nt][0], acc[mt][nt][1]);
                    split_store(Cs, planeCs, ldcs, row + 8, col,
                                acc[mt][nt][2], acc[mt][nt][3]);
                }
            } else {
                float2 g0 = *reinterpret_cast<const float2*>(C + (size_t)row * ldc + col);
                float2 g1 = *reinterpret_cast<const float2*>(C + (size_t)(row + 8) * ldc + col);
                split_store(Cs, planeCs, ldcs, row, col,
                            siluf(g0.x) * acc[mt][nt][0], siluf(g0.y) * acc[mt][nt][1]);
                split_store(Cs, planeCs, ldcs, row + 8, col,
                            siluf(g1.x) * acc[mt][nt][2], siluf(g1.y) * acc[mt][nt][3]);
            }
        }
    }
}

// ---------------------------------------------------------------------------
// fp32 -> bf16 (hi, lo) split, 2D grid, 4 cols/thread, no div/mod.
__global__ void split_kernel(const float* __restrict__ src, int src_ld,
                             int cols, int dstK,
                             __nv_bfloat16* __restrict__ dst, long long plane)
{
    int k0 = (blockIdx.x * blockDim.x + threadIdx.x) * 4;
    if (k0 >= dstK) return;
    int row = blockIdx.y;
    const float* s = src + (size_t)row * src_ld;
    __nv_bfloat16 hi[4], lo[4];
#pragma unroll
    for (int j = 0; j < 4; j++) {
        int k = k0 + j;
        float v = (k < cols) ? s[k] : 0.f;
        hi[j] = __float2bfloat16(v);
        lo[j] = __float2bfloat16(v - __bfloat162float(hi[j]));
    }
    size_t off = (size_t)row * dstK + k0;
    *reinterpret_cast<__nv_bfloat162*>(dst + off)     = __halves2bfloat162(hi[0], hi[1]);
    *reinterpret_cast<__nv_bfloat162*>(dst + off + 2) = __halves2bfloat162(hi[2], hi[3]);
    *reinterpret_cast<__nv_bfloat162*>(dst + off + plane)     = __halves2bfloat162(lo[0], lo[1]);
    *reinterpret_cast<__nv_bfloat162*>(dst + off + plane + 2) = __halves2bfloat162(lo[2], lo[3]);
}

__global__ void logits_kernel(const float* __restrict__ x,
                              const float* __restrict__ gw,
                              float* __restrict__ out)
{
    int warp = (blockIdx.x * blockDim.x + threadIdx.x) >> 5;
    int lane = threadIdx.x & 31;
    if (warp >= NTOK) return;
    const float* xr = x + (size_t)warp * HDIM;
    float acc[8] = {0.f, 0.f, 0.f, 0.f, 0.f, 0.f, 0.f, 0.f};
    for (int k = lane; k < HDIM; k += 32) {
        float xv = xr[k];
#pragma unroll
        for (int e = 0; e < 8; e++) acc[e] += xv * gw[e * HDIM + k];
    }
#pragma unroll
    for (int e = 0; e < 8; e++) {
        float v = acc[e];
#pragma unroll
        for (int o = 16; o; o >>= 1) v += __shfl_xor_sync(0xFFFFFFFFu, v, o);
        if (lane == 0) out[(size_t)warp * 8 + e] = v;
    }
}

// ---------------------------------------------------------------------------
static inline void run_split(const float* src, int src_ld, int rows,
                             int cols, int dstK, __nv_bfloat16* dst)
{
    long long plane = (long long)rows * dstK;
    dim3 grid((unsigned)((dstK + 1023) / 1024), (unsigned)rows);
    split_kernel<<<grid, 256>>>(src, src_ld, cols, dstK, dst, plane);
}

extern "C" void kernel_launch(void* const* d_in, const int* in_sizes, int n_in,
                              void* d_out, int out_size)
{
    const float* x  = (const float*)d_in[0];
    const float* gw = (const float*)d_in[1];
    const float* w1 = (const float*)d_in[2];
    const float* w2 = (const float*)d_in[3];
    const float* w3 = (const float*)d_in[4];
    const float* u1 = (const float*)d_in[5];
    const float* v1 = (const float*)d_in[6];
    const float* u2 = (const float*)d_in[7];
    const float* v2 = (const float*)d_in[8];
    const float* u3 = (const float*)d_in[9];
    const float* v3 = (const float*)d_in[10];

    float* out    = (float*)d_out;
    float* logits = out + (size_t)NTOK * HDIM;

    __nv_bfloat16 *xs, *w1s, *w3s, *w2s, *v1s, *v3s, *v2s, *u1s, *u3s, *u2s;
    __nv_bfloat16 *hs, *t1s, *t3s, *t2s;
    float* gate;
    cudaGetSymbolAddress((void**)&xs,  g_xs);
    cudaGetSymbolAddress((void**)&w1s, g_w1s);
    cudaGetSymbolAddress((void**)&w3s, g_w3s);
    cudaGetSymbolAddress((void**)&w2s, g_w2s);
    cudaGetSymbolAddress((void**)&v1s, g_v1s);
    cudaGetSymbolAddress((void**)&v3s, g_v3s);
    cudaGetSymbolAddress((void**)&v2s, g_v2s);
    cudaGetSymbolAddress((void**)&u1s, g_u1s);
    cudaGetSymbolAddress((void**)&u3s, g_u3s);
    cudaGetSymbolAddress((void**)&u2s, g_u2s);
    cudaGetSymbolAddress((void**)&hs,  g_hs);
    cudaGetSymbolAddress((void**)&t1s, g_t1s);
    cudaGetSymbolAddress((void**)&t3s, g_t3s);
    cudaGetSymbolAddress((void**)&t2s, g_t2s);
    cudaGetSymbolAddress((void**)&gate, g_gate);

    cudaFuncSetAttribute(mmagemm<0>, cudaFuncAttributeMaxDynamicSharedMemorySize, SMEM_TOTAL);
    cudaFuncSetAttribute(mmagemm<1>, cudaFuncAttributeMaxDynamicSharedMemorySize, SMEM_TOTAL);
    cudaFuncSetAttribute(mmagemm<2>, cudaFuncAttributeMaxDynamicSharedMemorySize, SMEM_TOTAL);

    // ---- input splits ------------------------------------------------------
    run_split(x,  HDIM, NTOK, HDIM, HDIM, xs);
    run_split(w1, HDIM, IDIM, HDIM, HDIM, w1s);
    run_split(w3, HDIM, IDIM, HDIM, HDIM, w3s);
    run_split(w2, IDIM, HDIM, IDIM, IDIM, w2s);
    run_split(v1, HDIM, RDIM, HDIM, HDIM, v1s);
    run_split(v3, HDIM, RDIM, HDIM, HDIM, v3s);
    run_split(v2, IDIM, RDIM, IDIM, IDIM, v2s);
    run_split(u1, RDIM, IDIM, RDIM, RPAD, u1s);
    run_split(u3, RDIM, IDIM, RDIM, RPAD, u3s);
    run_split(u2, RDIM, HDIM, RDIM, RPAD, u2s);

    const long long pX  = (long long)NTOK * HDIM;
    const long long pW1 = (long long)IDIM * HDIM;
    const long long pW2 = (long long)HDIM * IDIM;
    const long long pV1 = (long long)RDIM * HDIM;
    const long long pV2 = (long long)RDIM * IDIM;
    const long long pU1 = (long long)IDIM * RPAD;
    const long long pU2 = (long long)HDIM * RPAD;
    const long long pH  = (long long)NTOK * IDIM;
    const long long pT  = (long long)NTOK * RPAD;

    dim3 blk(256);
    dim3 gR((RDIM + BN - 1) / BN, NTOK / BM);   // (4, 64)
    dim3 gI(IDIM / BN, NTOK / BM);              // (56, 64)
    dim3 gH(HDIM / BN, NTOK / BM);              // (16, 64)

    // t1 = x@v1^T ; t3 = x@v3^T  (direct split-plane output)
    mmagemm<1><<<gR, blk, SMEM_TOTAL>>>(xs, pX, HDIM, HDIM, v1s, pV1, HDIM,
                                        nullptr, 0, 0, 0, nullptr, 0, 0,
                                        nullptr, RDIM, 0, t1s, pT, RPAD);
    mmagemm<1><<<gR, blk, SMEM_TOTAL>>>(xs, pX, HDIM, HDIM, v3s, pV1, HDIM,
                                        nullptr, 0, 0, 0, nullptr, 0, 0,
                                        nullptr, RDIM, 0, t3s, pT, RPAD);

    // gate = x@w1^T + t1@u1^T  (fp32)
    mmagemm<0><<<gI, blk, SMEM_TOTAL>>>(xs, pX, HDIM, HDIM, w1s, pW1, HDIM,
                                        t1s, pT, RPAD, RPAD, u1s, pU1, RPAD,
                                        gate, IDIM, IDIM, nullptr, 0, 0);
    // up GEMM fused: h = silu(gate)*up -> split planes
    mmagemm<2><<<gI, blk, SMEM_TOTAL>>>(xs, pX, HDIM, HDIM, w3s, pW1, HDIM,
                                        t3s, pT, RPAD, RPAD, u3s, pU1, RPAD,
                                        gate, IDIM, IDIM, hs, pH, IDIM);

    // t2 = h@v2^T  (direct split-plane output)
    mmagemm<1><<<gR, blk, SMEM_TOTAL>>>(hs, pH, IDIM, IDIM, v2s, pV2, IDIM,
                                        nullptr, 0, 0, 0, nullptr, 0, 0,
                                        nullptr, RDIM, 0, t2s, pT, RPAD);

    // out = h@w2^T + t2@u2^T  (fp32 -> d_out)
    mmagemm<0><<<gH, blk, SMEM_TOTAL>>>(hs, pH, IDIM, IDIM, w2s, pW2, IDIM,
                                        t2s, pT, RPAD, RPAD, u2s, pU2, RPAD,
                                        out, HDIM, HDIM, nullptr, 0, 0);

    // router logits
    {
        int tpb = 256;
        unsigned nb = (unsigned)((NTOK * 32 + tpb - 1) / tpb);
        logits_kernel<<<nb, tpb>>>(x, gw, logits);
    }
}

// round 5
// speedup vs baseline: 4.6391x; 1.2552x over previous
#include <cuda_runtime.h>
#include <cuda_bf16.h>
#include <cstdint>
#include <cstddef>

// ---------------------------------------------------------------------------
// Merge_MixtralSparseMoeBlock — weight-folded formulation:
//   W1' = w1 + u1@v1 ; W3' = w3 + u3@v3 ; W2' = w2 + u2@v2   (tiny prep GEMMs)
//   gate = x@W1'^T ; up = x@W3'^T   (one fused kernel, shared A tiles)
//   h = silu(gate)*up  (fused epilogue -> bf16 hi/lo planes)
//   out = h@W2'^T ; logits = x@gate_w^T
// All GEMMs: bf16 hi/lo split, 3 passes (hi*hi + hi*lo + lo*hi) in fp32.
// ---------------------------------------------------------------------------

#define NTOK 8192
#define HDIM 2048
#define IDIM 7168
#define RDIM 398
#define RPAD 448

// ---------------- device scratch -------------------------------------------
__device__ __align__(16) __nv_bfloat16 g_xs  [2ull * NTOK * HDIM];
__device__ __align__(16) __nv_bfloat16 g_u1s [2ull * IDIM * RPAD];
__device__ __align__(16) __nv_bfloat16 g_u3s [2ull * IDIM * RPAD];
__device__ __align__(16) __nv_bfloat16 g_u2s [2ull * HDIM * RPAD];
__device__ __align__(16) __nv_bfloat16 g_v1ts[2ull * HDIM * RPAD];
__device__ __align__(16) __nv_bfloat16 g_v3ts[2ull * HDIM * RPAD];
__device__ __align__(16) __nv_bfloat16 g_v2ts[2ull * IDIM * RPAD];
__device__ __align__(16) __nv_bfloat16 g_w1ps[2ull * IDIM * HDIM];
__device__ __align__(16) __nv_bfloat16 g_w3ps[2ull * IDIM * HDIM];
__device__ __align__(16) __nv_bfloat16 g_w2ps[2ull * HDIM * IDIM];
__device__ __align__(16) __nv_bfloat16 g_hs  [2ull * NTOK * IDIM];

// ---------------- PTX helpers ----------------------------------------------
__device__ __forceinline__ uint32_t smem_u32(const void* p) {
    uint32_t a;
    asm("{ .reg .u64 t; cvta.to.shared.u64 t, %1; cvt.u32.u64 %0, t; }"
        : "=r"(a) : "l"(p));
    return a;
}
__device__ __forceinline__ void ldsm_x4(uint32_t* r, uint32_t addr) {
    asm volatile("ldmatrix.sync.aligned.m8n8.x4.shared.b16 {%0,%1,%2,%3}, [%4];"
                 : "=r"(r[0]), "=r"(r[1]), "=r"(r[2]), "=r"(r[3]) : "r"(addr));
}
__device__ __forceinline__ void mma_bf16(float* d, const uint32_t* a, const uint32_t* b) {
    asm volatile("mma.sync.aligned.m16n8k16.row.col.f32.bf16.bf16.f32 "
                 "{%0,%1,%2,%3}, {%4,%5,%6,%7}, {%8,%9}, {%0,%1,%2,%3};"
                 : "+f"(d[0]), "+f"(d[1]), "+f"(d[2]), "+f"(d[3])
                 : "r"(a[0]), "r"(a[1]), "r"(a[2]), "r"(a[3]),
                   "r"(b[0]), "r"(b[1]));
}
#define CP_COMMIT() asm volatile("cp.async.commit_group;" ::: "memory")
#define CP_WAIT1()  asm volatile("cp.async.wait_group 1;" ::: "memory")

// BK=64 rows are 128B (8 x 16B chunks); chunk' = c ^ (r&7) is conflict-free.
__device__ __forceinline__ uint32_t swz(int r, int c) {
    return (uint32_t)(r * 128 + ((c ^ (r & 7)) << 4));
}

__device__ __forceinline__ float siluf(float x) { return x / (1.f + __expf(-x)); }

__device__ __forceinline__ void split_store(__nv_bfloat16* Cs, long long plane,
                                            int ldcs, int row, int col,
                                            float v0, float v1) {
    __nv_bfloat16 h0 = __float2bfloat16(v0), h1 = __float2bfloat16(v1);
    __nv_bfloat16 l0 = __float2bfloat16(v0 - __bfloat162float(h0));
    __nv_bfloat16 l1 = __float2bfloat16(v1 - __bfloat162float(h1));
    size_t off = (size_t)row * ldcs + col;
    *reinterpret_cast<__nv_bfloat162*>(Cs + off)         = __halves2bfloat162(h0, h1);
    *reinterpret_cast<__nv_bfloat162*>(Cs + off + plane) = __halves2bfloat162(l0, l1);
}

#define BM 128
#define BN 128
#define BK 64
#define STAGES 3
#define PLANE_BYTES  16384
#define STAGE_BYTES  (4 * PLANE_BYTES)
#define SMEM_TOTAL   (STAGES * STAGE_BYTES)    // 192 KB

__device__ __forceinline__ void load_plane(const __nv_bfloat16* __restrict__ g,
                                           int ld, int row0, int rowsValid,
                                           int k0, uint32_t sbase, int t) {
#pragma unroll
    for (int i = 0; i < 4; i++) {
        int idx = i * 256 + t;
        int r = idx >> 3;
        int c = idx & 7;
        int gr = row0 + r;
        bool ok = (gr < rowsValid);
        const void* gp = ok ? (const void*)(g + (size_t)gr * ld + k0 + c * 8)
                            : (const void*)g;
        uint32_t sp = sbase + swz(r, c);
        int sz = ok ? 16 : 0;
        asm volatile("cp.async.cg.shared.global [%0], [%1], 16, %2;"
                     :: "r"(sp), "l"(gp), "r"(sz));
    }
}
// 64-row tile (for fused kernel's B operands)
__device__ __forceinline__ void load_plane64(const __nv_bfloat16* __restrict__ g,
                                             int ld, int row0, int k0,
                                             uint32_t sbase, int t) {
#pragma unroll
    for (int i = 0; i < 2; i++) {
        int idx = i * 256 + t;
        int r = idx >> 3;          // 0..63
        int c = idx & 7;
        const void* gp = (const void*)(g + (size_t)(row0 + r) * ld + k0 + c * 8);
        uint32_t sp = sbase + swz(r, c);
        asm volatile("cp.async.cg.shared.global [%0], [%1], 16, 16;"
                     :: "r"(sp), "l"(gp));
    }
}

// ---------------------------------------------------------------------------
// Generic GEMM. MODE 0: C fp32 out. MODE 1: Cs planes = split(acc + Csrc).
template <int MODE>
__global__ __launch_bounds__(256, 1)
void mmagemm(const __nv_bfloat16* __restrict__ A1, long long planeA1, int lda1, int K1,
             const __nv_bfloat16* __restrict__ B1, long long planeB1, int ldb1,
             float* __restrict__ C, int N, int ldc,
             __nv_bfloat16* __restrict__ Cs, long long planeCs, int ldcs)
{
    extern __shared__ char smem[];
    const int t    = threadIdx.x;
    const int lane = t & 31;
    const int wid  = t >> 5;
    const int wm   = wid & 3;
    const int wn   = wid >> 2;
    const int m0   = blockIdx.y * BM;
    const int n0   = blockIdx.x * BN;
    const uint32_t sb0 = smem_u32(smem);
    const int CT = K1 >> 6;

    float acc[2][8][4];
#pragma unroll
    for (int i = 0; i < 2; i++)
#pragma unroll
        for (int j = 0; j < 8; j++)
#pragma unroll
            for (int k = 0; k < 4; k++) acc[i][j][k] = 0.f;

    int amask[2]; uint32_t aoffr[2];
#pragma unroll
    for (int mt = 0; mt < 2; mt++) {
        int ar = wm * 32 + mt * 16 + (lane & 15);
        aoffr[mt] = (uint32_t)ar * 128;
        amask[mt] = ar & 7;
    }
    const int alo = lane >> 4;
    const int gq  = lane >> 3;
    int bmask[4]; uint32_t boffr[4];
#pragma unroll
    for (int nq = 0; nq < 4; nq++) {
        int nr = wn * 64 + nq * 16 + (lane & 7) + ((gq & 2) << 2);
        boffr[nq] = (uint32_t)nr * 128;
        bmask[nq] = nr & 7;
    }
    const int blo = gq & 1;

    auto issue = [&](int cc, int stage) {
        int k0 = cc * BK;
        uint32_t sb = sb0 + stage * STAGE_BYTES;
        load_plane(A1,           lda1, m0, 1 << 30, k0, sb,                   t);
        load_plane(A1 + planeA1, lda1, m0, 1 << 30, k0, sb + PLANE_BYTES,     t);
        load_plane(B1,           ldb1, n0, N,       k0, sb + 2 * PLANE_BYTES, t);
        load_plane(B1 + planeB1, ldb1, n0, N,       k0, sb + 3 * PLANE_BYTES, t);
    };

    issue(0, 0); CP_COMMIT();
    if (CT > 1) issue(1, 1);
    CP_COMMIT();

#pragma unroll 1
    for (int cc = 0; cc < CT; cc++) {
        CP_WAIT1();
        __syncthreads();

        const uint32_t sb = sb0 + (cc % STAGES) * STAGE_BYTES;
        const uint32_t sAh = sb, sAl = sb + PLANE_BYTES;
        const uint32_t sBh = sb + 2 * PLANE_BYTES, sBl = sb + 3 * PLANE_BYTES;

#pragma unroll
        for (int ks = 0; ks < 4; ks++) {
            uint32_t ah[2][4], al[2][4], bh[8][2], bl[8][2];
            const int ac = ks * 2 + alo;
            const int bc = ks * 2 + blo;
#pragma unroll
            for (int mt = 0; mt < 2; mt++) {
                uint32_t ao = aoffr[mt] + (uint32_t)((ac ^ amask[mt]) << 4);
                ldsm_x4(ah[mt], sAh + ao);
                ldsm_x4(al[mt], sAl + ao);
            }
#pragma unroll
            for (int nq = 0; nq < 4; nq++) {
                uint32_t bo = boffr[nq] + (uint32_t)((bc ^ bmask[nq]) << 4);
                uint32_t r[4];
                ldsm_x4(r, sBh + bo);
                bh[nq * 2][0] = r[0]; bh[nq * 2][1] = r[1];
                bh[nq * 2 + 1][0] = r[2]; bh[nq * 2 + 1][1] = r[3];
                ldsm_x4(r, sBl + bo);
                bl[nq * 2][0] = r[0]; bl[nq * 2][1] = r[1];
                bl[nq * 2 + 1][0] = r[2]; bl[nq * 2 + 1][1] = r[3];
            }
#pragma unroll
            for (int mt = 0; mt < 2; mt++)
#pragma unroll
                for (int nt = 0; nt < 8; nt++) mma_bf16(acc[mt][nt], ah[mt], bh[nt]);
#pragma unroll
            for (int mt = 0; mt < 2; mt++)
#pragma unroll
                for (int nt = 0; nt < 8; nt++) mma_bf16(acc[mt][nt], ah[mt], bl[nt]);
#pragma unroll
            for (int mt = 0; mt < 2; mt++)
#pragma unroll
                for (int nt = 0; nt < 8; nt++) mma_bf16(acc[mt][nt], al[mt], bh[nt]);
        }
        __syncthreads();

        int nc = cc + STAGES - 1;
        if (nc < CT) issue(nc, nc % STAGES);
        CP_COMMIT();
    }

#pragma unroll
    for (int mt = 0; mt < 2; mt++) {
        int row = m0 + wm * 32 + mt * 16 + (lane >> 2);
#pragma unroll
        for (int nt = 0; nt < 8; nt++) {
            int col = n0 + wn * 64 + nt * 8 + (lane & 3) * 2;
            if (col >= N) continue;
            if (MODE == 0) {
                *reinterpret_cast<float2*>(C + (size_t)row * ldc + col) =
                    make_float2(acc[mt][nt][0], acc[mt][nt][1]);
                *reinterpret_cast<float2*>(C + (size_t)(row + 8) * ldc + col) =
                    make_float2(acc[mt][nt][2], acc[mt][nt][3]);
            } else {
                float2 w0 = *reinterpret_cast<const float2*>(C + (size_t)row * ldc + col);
                float2 w1 = *reinterpret_cast<const float2*>(C + (size_t)(row + 8) * ldc + col);
                split_store(Cs, planeCs, ldcs, row, col,
                            acc[mt][nt][0] + w0.x, acc[mt][nt][1] + w0.y);
                split_store(Cs, planeCs, ldcs, row + 8, col,
                            acc[mt][nt][2] + w1.x, acc[mt][nt][3] + w1.y);
            }
        }
    }
}

// ---------------------------------------------------------------------------
// Fused gate+up kernel: A=xs shared; B1=W1' planes, B2=W3' planes (64 cols
// each); epilogue h = silu(gate)*up -> hs planes.
// SMEM stage: Ah(16K) Al(16K) B1h(8K) B1l(8K) B2h(8K) B2l(8K) = 64K.
#define FB1H (2 * PLANE_BYTES)
#define FB1L (FB1H + 8192)
#define FB2H (FB1L + 8192)
#define FB2L (FB2H + 8192)

__global__ __launch_bounds__(256, 1)
void fused_gateup(const __nv_bfloat16* __restrict__ xs, long long pX,
                  const __nv_bfloat16* __restrict__ w1p,
                  const __nv_bfloat16* __restrict__ w3p, long long pW,
                  __nv_bfloat16* __restrict__ hs, long long pH)
{
    extern __shared__ char smem[];
    const int t    = threadIdx.x;
    const int lane = t & 31;
    const int wid  = t >> 5;
    const int wm   = wid & 3;
    const int wn   = wid >> 2;
    const int m0   = blockIdx.y * BM;
    const int n0   = blockIdx.x * 64;
    const uint32_t sb0 = smem_u32(smem);
    const int CT = HDIM >> 6;     // 32

    float accG[2][4][4], accU[2][4][4];
#pragma unroll
    for (int i = 0; i < 2; i++)
#pragma unroll
        for (int j = 0; j < 4; j++)
#pragma unroll
            for (int k = 0; k < 4; k++) { accG[i][j][k] = 0.f; accU[i][j][k] = 0.f; }

    int amask[2]; uint32_t aoffr[2];
#pragma unroll
    for (int mt = 0; mt < 2; mt++) {
        int ar = wm * 32 + mt * 16 + (lane & 15);
        aoffr[mt] = (uint32_t)ar * 128;
        amask[mt] = ar & 7;
    }
    const int alo = lane >> 4;
    const int gq  = lane >> 3;
    int bmask[2]; uint32_t boffr[2];
#pragma unroll
    for (int nq = 0; nq < 2; nq++) {
        int nr = wn * 32 + nq * 16 + (lane & 7) + ((gq & 2) << 2);
        boffr[nq] = (uint32_t)nr * 128;
        bmask[nq] = nr & 7;
    }
    const int blo = gq & 1;

    auto issue = [&](int cc, int stage) {
        int k0 = cc * BK;
        uint32_t sb = sb0 + stage * STAGE_BYTES;
        load_plane(xs,      HDIM, m0, 1 << 30, k0, sb,               t);
        load_plane(xs + pX, HDIM, m0, 1 << 30, k0, sb + PLANE_BYTES, t);
        load_plane64(w1p,      HDIM, n0, k0, sb + FB1H, t);
        load_plane64(w1p + pW, HDIM, n0, k0, sb + FB1L, t);
        load_plane64(w3p,      HDIM, n0, k0, sb + FB2H, t);
        load_plane64(w3p + pW, HDIM, n0, k0, sb + FB2L, t);
    };

    issue(0, 0); CP_COMMIT();
    issue(1, 1); CP_COMMIT();

#pragma unroll 1
    for (int cc = 0; cc < CT; cc++) {
        CP_WAIT1();
        __syncthreads();

        const uint32_t sb = sb0 + (cc % STAGES) * STAGE_BYTES;
        const uint32_t sAh = sb, sAl = sb + PLANE_BYTES;

#pragma unroll
        for (int ks = 0; ks < 4; ks++) {
            uint32_t ah[2][4], al[2][4];
            uint32_t b1h[4][2], b1l[4][2], b2h[4][2], b2l[4][2];
            const int ac = ks * 2 + alo;
            const int bc = ks * 2 + blo;
#pragma unroll
            for (int mt = 0; mt < 2; mt++) {
                uint32_t ao = aoffr[mt] + (uint32_t)((ac ^ amask[mt]) << 4);
                ldsm_x4(ah[mt], sAh + ao);
                ldsm_x4(al[mt], sAl + ao);
            }
#pragma unroll
            for (int nq = 0; nq < 2; nq++) {
                uint32_t bo = boffr[nq] + (uint32_t)((bc ^ bmask[nq]) << 4);
                uint32_t r[4];
                ldsm_x4(r, sb + FB1H + bo);
                b1h[nq * 2][0] = r[0]; b1h[nq * 2][1] = r[1];
                b1h[nq * 2 + 1][0] = r[2]; b1h[nq * 2 + 1][1] = r[3];
                ldsm_x4(r, sb + FB1L + bo);
                b1l[nq * 2][0] = r[0]; b1l[nq * 2][1] = r[1];
                b1l[nq * 2 + 1][0] = r[2]; b1l[nq * 2 + 1][1] = r[3];
                ldsm_x4(r, sb + FB2H + bo);
                b2h[nq * 2][0] = r[0]; b2h[nq * 2][1] = r[1];
                b2h[nq * 2 + 1][0] = r[2]; b2h[nq * 2 + 1][1] = r[3];
                ldsm_x4(r, sb + FB2L + bo);
                b2l[nq * 2][0] = r[0]; b2l[nq * 2][1] = r[1];
                b2l[nq * 2 + 1][0] = r[2]; b2l[nq * 2 + 1][1] = r[3];
            }
            // interleave G/U so accumulator reuse distance = 16
#pragma unroll
            for (int mt = 0; mt < 2; mt++)
#pragma unroll
                for (int nt = 0; nt < 4; nt++) mma_bf16(accG[mt][nt], ah[mt], b1h[nt]);
#pragma unroll
            for (int mt = 0; mt < 2; mt++)
#pragma unroll
                for (int nt = 0; nt < 4; nt++) mma_bf16(accU[mt][nt], ah[mt], b2h[nt]);
#pragma unroll
            for (int mt = 0; mt < 2; mt++)
#pragma unroll
                for (int nt = 0; nt < 4; nt++) mma_bf16(accG[mt][nt], ah[mt], b1l[nt]);
#pragma unroll
            for (int mt = 0; mt < 2; mt++)
#pragma unroll
                for (int nt = 0; nt < 4; nt++) mma_bf16(accU[mt][nt], ah[mt], b2l[nt]);
#pragma unroll
            for (int mt = 0; mt < 2; mt++)
#pragma unroll
                for (int nt = 0; nt < 4; nt++) mma_bf16(accG[mt][nt], al[mt], b1h[nt]);
#pragma unroll
            for (int mt = 0; mt < 2; mt++)
#pragma unroll
                for (int nt = 0; nt < 4; nt++) mma_bf16(accU[mt][nt], al[mt], b2h[nt]);
        }
        __syncthreads();

        int nc = cc + STAGES - 1;
        if (nc < CT) issue(nc, nc % STAGES);
        CP_COMMIT();
    }

    // epilogue: h = silu(gate)*up -> split planes
#pragma unroll
    for (int mt = 0; mt < 2; mt++) {
        int row = m0 + wm * 32 + mt * 16 + (lane >> 2);
#pragma unroll
        for (int nt = 0; nt < 4; nt++) {
            int col = n0 + wn * 32 + nt * 8 + (lane & 3) * 2;
            float h00 = siluf(accG[mt][nt][0]) * accU[mt][nt][0];
            float h01 = siluf(accG[mt][nt][1]) * accU[mt][nt][1];
            float h10 = siluf(accG[mt][nt][2]) * accU[mt][nt][2];
            float h11 = siluf(accG[mt][nt][3]) * accU[mt][nt][3];
            split_store(hs, pH, IDIM, row,     col, h00, h01);
            split_store(hs, pH, IDIM, row + 8, col, h10, h11);
        }
    }
}

// ---------------------------------------------------------------------------
__global__ void split_kernel(const float* __restrict__ src, int src_ld,
                             int cols, int dstK,
                             __nv_bfloat16* __restrict__ dst, long long plane)
{
    int k0 = (blockIdx.x * blockDim.x + threadIdx.x) * 4;
    if (k0 >= dstK) return;
    int row = blockIdx.y;
    const float* s = src + (size_t)row * src_ld;
    __nv_bfloat16 hi[4], lo[4];
#pragma unroll
    for (int j = 0; j < 4; j++) {
        int k = k0 + j;
        float v = (k < cols) ? s[k] : 0.f;
        hi[j] = __float2bfloat16(v);
        lo[j] = __float2bfloat16(v - __bfloat162float(hi[j]));
    }
    size_t off = (size_t)row * dstK + k0;
    *reinterpret_cast<__nv_bfloat162*>(dst + off)     = __halves2bfloat162(hi[0], hi[1]);
    *reinterpret_cast<__nv_bfloat162*>(dst + off + 2) = __halves2bfloat162(hi[2], hi[3]);
    *reinterpret_cast<__nv_bfloat162*>(dst + off + plane)     = __halves2bfloat162(lo[0], lo[1]);
    *reinterpret_cast<__nv_bfloat162*>(dst + off + plane + 2) = __halves2bfloat162(lo[2], lo[3]);
}

// transpose + split: src[r, c] (r < rows, ld = C) -> dst[c * RPAD + r] planes.
__global__ void tsplit_kernel(const float* __restrict__ src, int C, int rows,
                              __nv_bfloat16* __restrict__ dst, long long plane)
{
    __shared__ float sm[32][33];
    int c0 = blockIdx.x * 32, r0 = blockIdx.y * 32;
    int tx = threadIdx.x, ty = threadIdx.y;
    int r = r0 + ty;
    float v = (r < rows) ? src[(size_t)r * C + c0 + tx] : 0.f;
    sm[ty][tx] = v;
    __syncthreads();
    float w = sm[tx][ty];
    __nv_bfloat16 hi = __float2bfloat16(w);
    __nv_bfloat16 lo = __float2bfloat16(w - __bfloat162float(hi));
    size_t off = (size_t)(c0 + ty) * RPAD + r0 + tx;
    dst[off] = hi;
    dst[off + plane] = lo;
}

__global__ void logits_kernel(const float* __restrict__ x,
                              const float* __restrict__ gw,
                              float* __restrict__ out)
{
    int warp = (blockIdx.x * blockDim.x + threadIdx.x) >> 5;
    int lane = threadIdx.x & 31;
    if (warp >= NTOK) return;
    const float* xr = x + (size_t)warp * HDIM;
    float acc[8] = {0.f, 0.f, 0.f, 0.f, 0.f, 0.f, 0.f, 0.f};
    for (int k = lane; k < HDIM; k += 32) {
        float xv = xr[k];
#pragma unroll
        for (int e = 0; e < 8; e++) acc[e] += xv * gw[e * HDIM + k];
    }
#pragma unroll
    for (int e = 0; e < 8; e++) {
        float v = acc[e];
#pragma unroll
        for (int o = 16; o; o >>= 1) v += __shfl_xor_sync(0xFFFFFFFFu, v, o);
        if (lane == 0) out[(size_t)warp * 8 + e] = v;
    }
}

// ---------------------------------------------------------------------------
static inline void run_split(const float* src, int src_ld, int rows,
                             int cols, int dstK, __nv_bfloat16* dst)
{
    long long plane = (long long)rows * dstK;
    dim3 grid((unsigned)((dstK + 1023) / 1024), (unsigned)rows);
    split_kernel<<<grid, 256>>>(src, src_ld, cols, dstK, dst, plane);
}
static inline void run_tsplit(const float* src, int C, int rows, __nv_bfloat16* dst)
{
    long long plane = (long long)C * RPAD;
    dim3 grid((unsigned)(C / 32), RPAD / 32);
    tsplit_kernel<<<grid, dim3(32, 32)>>>(src, C, rows, dst, plane);
}

extern "C" void kernel_launch(void* const* d_in, const int* in_sizes, int n_in,
                              void* d_out, int out_size)
{
    const float* x  = (const float*)d_in[0];
    const float* gw = (const float*)d_in[1];
    const float* w1 = (const float*)d_in[2];
    const float* w2 = (const float*)d_in[3];
    const float* w3 = (const float*)d_in[4];
    const float* u1 = (const float*)d_in[5];
    const float* v1 = (const float*)d_in[6];
    const float* u2 = (const float*)d_in[7];
    const float* v2 = (const float*)d_in[8];
    const float* u3 = (const float*)d_in[9];
    const float* v3 = (const float*)d_in[10];

    float* out    = (float*)d_out;
    float* logits = out + (size_t)NTOK * HDIM;

    __nv_bfloat16 *xs, *u1s, *u3s, *u2s, *v1ts, *v3ts, *v2ts;
    __nv_bfloat16 *w1ps, *w3ps, *w2ps, *hs;
    cudaGetSymbolAddress((void**)&xs,   g_xs);
    cudaGetSymbolAddress((void**)&u1s,  g_u1s);
    cudaGetSymbolAddress((void**)&u3s,  g_u3s);
    cudaGetSymbolAddress((void**)&u2s,  g_u2s);
    cudaGetSymbolAddress((void**)&v1ts, g_v1ts);
    cudaGetSymbolAddress((void**)&v3ts, g_v3ts);
    cudaGetSymbolAddress((void**)&v2ts, g_v2ts);
    cudaGetSymbolAddress((void**)&w1ps, g_w1ps);
    cudaGetSymbolAddress((void**)&w3ps, g_w3ps);
    cudaGetSymbolAddress((void**)&w2ps, g_w2ps);
    cudaGetSymbolAddress((void**)&hs,   g_hs);

    cudaFuncSetAttribute(mmagemm<0>, cudaFuncAttributeMaxDynamicSharedMemorySize, SMEM_TOTAL);
    cudaFuncSetAttribute(mmagemm<1>, cudaFuncAttributeMaxDynamicSharedMemorySize, SMEM_TOTAL);
    cudaFuncSetAttribute(fused_gateup, cudaFuncAttributeMaxDynamicSharedMemorySize, SMEM_TOTAL);

    // ---- splits / transposes ----------------------------------------------
    run_split(x,  HDIM, NTOK, HDIM, HDIM, xs);
    run_split(u1, RDIM, IDIM, RDIM, RPAD, u1s);
    run_split(u3, RDIM, IDIM, RDIM, RPAD, u3s);
    run_split(u2, RDIM, HDIM, RDIM, RPAD, u2s);
    run_tsplit(v1, HDIM, RDIM, v1ts);
    run_tsplit(v3, HDIM, RDIM, v3ts);
    run_tsplit(v2, IDIM, RDIM, v2ts);

    const long long pX   = (long long)NTOK * HDIM;
    const long long pU1  = (long long)IDIM * RPAD;   // u1s/u3s, also v2ts
    const long long pU2  = (long long)HDIM * RPAD;   // u2s, also v1ts/v3ts
    const long long pW1  = (long long)IDIM * HDIM;   // w1ps/w3ps
    const long long pW2  = (long long)HDIM * IDIM;   // w2ps
    const long long pH   = (long long)NTOK * IDIM;

    dim3 blk(256);

    // ---- weight folding: W' = w + u@v  (MODE 1: acc + src -> planes) ------
    // W1'[I,H]: A=u1s [I,RPAD], B=v1ts [H,RPAD]
    mmagemm<1><<<dim3(HDIM / BN, IDIM / BM), blk, SMEM_TOTAL>>>(
        u1s, pU1, RPAD, RPAD, v1ts, pU2, RPAD,
        (float*)w1, HDIM, HDIM, w1ps, pW1, HDIM);
    mmagemm<1><<<dim3(HDIM / BN, IDIM / BM), blk, SMEM_TOTAL>>>(
        u3s, pU1, RPAD, RPAD, v3ts, pU2, RPAD,
        (float*)w3, HDIM, HDIM, w3ps, pW1, HDIM);
    // W2'[H,I]: A=u2s [H,RPAD], B=v2ts [I,RPAD]
    mmagemm<1><<<dim3(IDIM / BN, HDIM / BM), blk, SMEM_TOTAL>>>(
        u2s, pU2, RPAD, RPAD, v2ts, pU1, RPAD,
        (float*)w2, IDIM, IDIM, w2ps, pW2, IDIM);

    // ---- fused gate/up + silu -> h planes ---------------------------------
    fused_gateup<<<dim3(IDIM / 64, NTOK / BM), blk, SMEM_TOTAL>>>(
        xs, pX, w1ps, w3ps, pW1, hs, pH);

    // ---- out = h @ W2'^T --------------------------------------------------
    mmagemm<0><<<dim3(HDIM / BN, NTOK / BM), blk, SMEM_TOTAL>>>(
        hs, pH, IDIM, IDIM, w2ps, pW2, IDIM,
        out, HDIM, HDIM, nullptr, 0, 0);

    // ---- router logits ----------------------------------------------------
    {
        int tpb = 256;
        unsigned nb = (unsigned)((NTOK * 32 + tpb - 1) / tpb);
        logits_kernel<<<nb, tpb>>>(x, gw, logits);
    }
}

// round 6
// speedup vs baseline: 4.7746x; 1.0292x over previous
#include <cuda_runtime.h>
#include <cuda_bf16.h>
#include <cstdint>
#include <cstddef>

// ---------------------------------------------------------------------------
// Merge_MixtralSparseMoeBlock — weight-folded, bf16 hi/lo split (3 passes):
//   W1' = w1 + u1@v1 ; W3' = w3 + u3@v3 ; W2' = w2 + u2@v2   (one prep launch)
//   gate = x@W1'^T ; up = x@W3'^T  (fused, shared A tiles)
//   h = silu(gate)*up  (fused epilogue -> bf16 hi/lo planes)
//   out = h@W2'^T ; logits = x@gate_w^T
// ---------------------------------------------------------------------------

#define NTOK 8192
#define HDIM 2048
#define IDIM 7168
#define RDIM 398
#define RPAD 448

// ---------------- device scratch -------------------------------------------
__device__ __align__(16) __nv_bfloat16 g_xs  [2ull * NTOK * HDIM];
__device__ __align__(16) __nv_bfloat16 g_u1s [2ull * IDIM * RPAD];
__device__ __align__(16) __nv_bfloat16 g_u3s [2ull * IDIM * RPAD];
__device__ __align__(16) __nv_bfloat16 g_u2s [2ull * HDIM * RPAD];
__device__ __align__(16) __nv_bfloat16 g_v1ts[2ull * HDIM * RPAD];
__device__ __align__(16) __nv_bfloat16 g_v3ts[2ull * HDIM * RPAD];
__device__ __align__(16) __nv_bfloat16 g_v2ts[2ull * IDIM * RPAD];
__device__ __align__(16) __nv_bfloat16 g_w1ps[2ull * IDIM * HDIM];
__device__ __align__(16) __nv_bfloat16 g_w3ps[2ull * IDIM * HDIM];
__device__ __align__(16) __nv_bfloat16 g_w2ps[2ull * HDIM * IDIM];
__device__ __align__(16) __nv_bfloat16 g_hs  [2ull * NTOK * IDIM];

// ---------------- PTX helpers ----------------------------------------------
__device__ __forceinline__ uint32_t smem_u32(const void* p) {
    uint32_t a;
    asm("{ .reg .u64 t; cvta.to.shared.u64 t, %1; cvt.u32.u64 %0, t; }"
        : "=r"(a) : "l"(p));
    return a;
}
__device__ __forceinline__ void ldsm_x4(uint32_t* r, uint32_t addr) {
    asm volatile("ldmatrix.sync.aligned.m8n8.x4.shared.b16 {%0,%1,%2,%3}, [%4];"
                 : "=r"(r[0]), "=r"(r[1]), "=r"(r[2]), "=r"(r[3]) : "r"(addr));
}
__device__ __forceinline__ void mma_bf16(float* d, const uint32_t* a, const uint32_t* b) {
    asm volatile("mma.sync.aligned.m16n8k16.row.col.f32.bf16.bf16.f32 "
                 "{%0,%1,%2,%3}, {%4,%5,%6,%7}, {%8,%9}, {%0,%1,%2,%3};"
                 : "+f"(d[0]), "+f"(d[1]), "+f"(d[2]), "+f"(d[3])
                 : "r"(a[0]), "r"(a[1]), "r"(a[2]), "r"(a[3]),
                   "r"(b[0]), "r"(b[1]));
}
#define CP_COMMIT() asm volatile("cp.async.commit_group;" ::: "memory")
#define CP_WAIT1()  asm volatile("cp.async.wait_group 1;" ::: "memory")

// BK=64 rows are 128B (8 x 16B chunks); chunk' = c ^ (r&7) is conflict-free.
__device__ __forceinline__ uint32_t swz(int r, int c) {
    return (uint32_t)(r * 128 + ((c ^ (r & 7)) << 4));
}
__device__ __forceinline__ float siluf(float x) { return x / (1.f + __expf(-x)); }

__device__ __forceinline__ void split_store(__nv_bfloat16* Cs, long long plane,
                                            int ldcs, int row, int col,
                                            float v0, float v1) {
    __nv_bfloat16 h0 = __float2bfloat16(v0), h1 = __float2bfloat16(v1);
    __nv_bfloat16 l0 = __float2bfloat16(v0 - __bfloat162float(h0));
    __nv_bfloat16 l1 = __float2bfloat16(v1 - __bfloat162float(h1));
    size_t off = (size_t)row * ldcs + col;
    *reinterpret_cast<__nv_bfloat162*>(Cs + off)         = __halves2bfloat162(h0, h1);
    *reinterpret_cast<__nv_bfloat162*>(Cs + off + plane) = __halves2bfloat162(l0, l1);
}

#define BM 128
#define BN 128
#define BK 64
#define STAGES 3
#define PLANE_BYTES  16384
#define STAGE_BYTES  (4 * PLANE_BYTES)
#define SMEM_TOTAL   (STAGES * STAGE_BYTES)    // 192 KB

__device__ __forceinline__ void load_plane(const __nv_bfloat16* __restrict__ g,
                                           int ld, int row0, int k0,
                                           uint32_t sbase, int t) {
#pragma unroll
    for (int i = 0; i < 4; i++) {
        int idx = i * 256 + t;
        int r = idx >> 3;
        int c = idx & 7;
        const void* gp = (const void*)(g + (size_t)(row0 + r) * ld + k0 + c * 8);
        uint32_t sp = sbase + swz(r, c);
        asm volatile("cp.async.cg.shared.global [%0], [%1], 16, 16;"
                     :: "r"(sp), "l"(gp));
    }
}
__device__ __forceinline__ void load_plane64(const __nv_bfloat16* __restrict__ g,
                                             int ld, int row0, int k0,
                                             uint32_t sbase, int t) {
#pragma unroll
    for (int i = 0; i < 2; i++) {
        int idx = i * 256 + t;
        int r = idx >> 3;
        int c = idx & 7;
        const void* gp = (const void*)(g + (size_t)(row0 + r) * ld + k0 + c * 8);
        uint32_t sp = sbase + swz(r, c);
        asm volatile("cp.async.cg.shared.global [%0], [%1], 16, 16;"
                     :: "r"(sp), "l"(gp));
    }
}

// ---------------------------------------------------------------------------
// Core 128x128 tile GEMM (device body).
// MODE 0: C fp32 out. MODE 1: Cs planes = split(acc + Csrc).
template <int MODE>
__device__ __forceinline__ void gemm_tile(
    const __nv_bfloat16* __restrict__ A1, long long planeA1, int lda1, int K1,
    const __nv_bfloat16* __restrict__ B1, long long planeB1, int ldb1,
    float* __restrict__ C, int ldc,
    __nv_bfloat16* __restrict__ Cs, long long planeCs, int ldcs,
    int m0, int n0, char* smem)
{
    const int t    = threadIdx.x;
    const int lane = t & 31;
    const int wid  = t >> 5;
    const int wm   = wid & 3;
    const int wn   = wid >> 2;
    const uint32_t sb0 = smem_u32(smem);
    const int CT = K1 >> 6;

    float acc[2][8][4];
#pragma unroll
    for (int i = 0; i < 2; i++)
#pragma unroll
        for (int j = 0; j < 8; j++)
#pragma unroll
            for (int k = 0; k < 4; k++) acc[i][j][k] = 0.f;

    int amask[2]; uint32_t aoffr[2];
#pragma unroll
    for (int mt = 0; mt < 2; mt++) {
        int ar = wm * 32 + mt * 16 + (lane & 15);
        aoffr[mt] = (uint32_t)ar * 128;
        amask[mt] = ar & 7;
    }
    const int alo = lane >> 4;
    const int gq  = lane >> 3;
    int bmask[4]; uint32_t boffr[4];
#pragma unroll
    for (int nq = 0; nq < 4; nq++) {
        int nr = wn * 64 + nq * 16 + (lane & 7) + ((gq & 2) << 2);
        boffr[nq] = (uint32_t)nr * 128;
        bmask[nq] = nr & 7;
    }
    const int blo = gq & 1;

    auto issue = [&](int cc, int stage) {
        int k0 = cc * BK;
        uint32_t sb = sb0 + stage * STAGE_BYTES;
        load_plane(A1,           lda1, m0, k0, sb,                   t);
        load_plane(A1 + planeA1, lda1, m0, k0, sb + PLANE_BYTES,     t);
        load_plane(B1,           ldb1, n0, k0, sb + 2 * PLANE_BYTES, t);
        load_plane(B1 + planeB1, ldb1, n0, k0, sb + 3 * PLANE_BYTES, t);
    };

    issue(0, 0); CP_COMMIT();
    if (CT > 1) issue(1, 1);
    CP_COMMIT();

#pragma unroll 1
    for (int cc = 0; cc < CT; cc++) {
        CP_WAIT1();
        __syncthreads();   // also covers: all warps done reading stage (cc-1)

        const uint32_t sb = sb0 + (cc % STAGES) * STAGE_BYTES;
        const uint32_t sAh = sb, sAl = sb + PLANE_BYTES;
        const uint32_t sBh = sb + 2 * PLANE_BYTES, sBl = sb + 3 * PLANE_BYTES;

#pragma unroll
        for (int ks = 0; ks < 4; ks++) {
            const int ac = ks * 2 + alo;
            const int bc = ks * 2 + blo;
            uint32_t ah[2][4], al[2][4], bh[8][2], bl[8][2];
            // batch 1: ah + bh, then pass1
#pragma unroll
            for (int mt = 0; mt < 2; mt++)
                ldsm_x4(ah[mt], sAh + aoffr[mt] + (uint32_t)((ac ^ amask[mt]) << 4));
#pragma unroll
            for (int nq = 0; nq < 4; nq++) {
                uint32_t r[4];
                ldsm_x4(r, sBh + boffr[nq] + (uint32_t)((bc ^ bmask[nq]) << 4));
                bh[nq * 2][0] = r[0]; bh[nq * 2][1] = r[1];
                bh[nq * 2 + 1][0] = r[2]; bh[nq * 2 + 1][1] = r[3];
            }
#pragma unroll
            for (int mt = 0; mt < 2; mt++)
#pragma unroll
                for (int nt = 0; nt < 8; nt++) mma_bf16(acc[mt][nt], ah[mt], bh[nt]);
            // batch 2: bl, then pass2 (ah*bl)
#pragma unroll
            for (int nq = 0; nq < 4; nq++) {
                uint32_t r[4];
                ldsm_x4(r, sBl + boffr[nq] + (uint32_t)((bc ^ bmask[nq]) << 4));
                bl[nq * 2][0] = r[0]; bl[nq * 2][1] = r[1];
                bl[nq * 2 + 1][0] = r[2]; bl[nq * 2 + 1][1] = r[3];
            }
#pragma unroll
            for (int mt = 0; mt < 2; mt++)
#pragma unroll
                for (int nt = 0; nt < 8; nt++) mma_bf16(acc[mt][nt], ah[mt], bl[nt]);
            // batch 3: al, then pass3 (al*bh)
#pragma unroll
            for (int mt = 0; mt < 2; mt++)
                ldsm_x4(al[mt], sAl + aoffr[mt] + (uint32_t)((ac ^ amask[mt]) << 4));
#pragma unroll
            for (int mt = 0; mt < 2; mt++)
#pragma unroll
                for (int nt = 0; nt < 8; nt++) mma_bf16(acc[mt][nt], al[mt], bh[nt]);
        }
        // no barrier needed: stage (cc+2)%3 readers all passed this iter's top
        int nc = cc + STAGES - 1;
        if (nc < CT) issue(nc, nc % STAGES);
        CP_COMMIT();
    }

#pragma unroll
    for (int mt = 0; mt < 2; mt++) {
        int row = m0 + wm * 32 + mt * 16 + (lane >> 2);
#pragma unroll
        for (int nt = 0; nt < 8; nt++) {
            int col = n0 + wn * 64 + nt * 8 + (lane & 3) * 2;
            if (MODE == 0) {
                *reinterpret_cast<float2*>(C + (size_t)row * ldc + col) =
                    make_float2(acc[mt][nt][0], acc[mt][nt][1]);
                *reinterpret_cast<float2*>(C + (size_t)(row + 8) * ldc + col) =
                    make_float2(acc[mt][nt][2], acc[mt][nt][3]);
            } else {
                float2 w0 = *reinterpret_cast<const float2*>(C + (size_t)row * ldc + col);
                float2 w1 = *reinterpret_cast<const float2*>(C + (size_t)(row + 8) * ldc + col);
                split_store(Cs, planeCs, ldcs, row, col,
                            acc[mt][nt][0] + w0.x, acc[mt][nt][1] + w0.y);
                split_store(Cs, planeCs, ldcs, row + 8, col,
                            acc[mt][nt][2] + w1.x, acc[mt][nt][3] + w1.y);
            }
        }
    }
}

// plane sizes (compile-time)
#define P_X   ((long long)NTOK * HDIM)
#define P_UI  ((long long)IDIM * RPAD)   // u1s/u3s, v2ts
#define P_UH  ((long long)HDIM * RPAD)   // u2s, v1ts/v3ts
#define P_W1  ((long long)IDIM * HDIM)   // w1ps/w3ps
#define P_W2  ((long long)HDIM * IDIM)   // w2ps
#define P_H   ((long long)NTOK * IDIM)

// Merged prep: z=0 W1', z=1 W3', z=2 W2'. Grid (56, 16, 3).
__global__ __launch_bounds__(256, 1)
void prep_kernel(const __nv_bfloat16* __restrict__ u1s,
                 const __nv_bfloat16* __restrict__ u3s,
                 const __nv_bfloat16* __restrict__ u2s,
                 const __nv_bfloat16* __restrict__ v1ts,
                 const __nv_bfloat16* __restrict__ v3ts,
                 const __nv_bfloat16* __restrict__ v2ts,
                 const float* __restrict__ w1, const float* __restrict__ w3,
                 const float* __restrict__ w2,
                 __nv_bfloat16* __restrict__ w1ps,
                 __nv_bfloat16* __restrict__ w3ps,
                 __nv_bfloat16* __restrict__ w2ps)
{
    extern __shared__ char smem[];
    if (blockIdx.z == 0) {
        gemm_tile<1>(u1s, P_UI, RPAD, RPAD, v1ts, P_UH, RPAD,
                     (float*)w1, HDIM, w1ps, P_W1, HDIM,
                     blockIdx.x * BM, blockIdx.y * BN, smem);
    } else if (blockIdx.z == 1) {
        gemm_tile<1>(u3s, P_UI, RPAD, RPAD, v3ts, P_UH, RPAD,
                     (float*)w3, HDIM, w3ps, P_W1, HDIM,
                     blockIdx.x * BM, blockIdx.y * BN, smem);
    } else {
        gemm_tile<1>(u2s, P_UH, RPAD, RPAD, v2ts, P_UI, RPAD,
                     (float*)w2, IDIM, w2ps, P_W2, IDIM,
                     blockIdx.y * BM, blockIdx.x * BN, smem);
    }
}

// Down GEMM: out = h @ W2'^T (fp32 out)
__global__ __launch_bounds__(256, 1)
void down_kernel(const __nv_bfloat16* __restrict__ hs,
                 const __nv_bfloat16* __restrict__ w2ps,
                 float* __restrict__ out)
{
    extern __shared__ char smem[];
    gemm_tile<0>(hs, P_H, IDIM, IDIM, w2ps, P_W2, IDIM,
                 out, HDIM, nullptr, 0, 0,
                 blockIdx.y * BM, blockIdx.x * BN, smem);
}

// ---------------------------------------------------------------------------
// Fused gate+up: A=xs; B1=W1', B2=W3' (64 cols each); h=silu(g)*u -> planes.
#define FB1H (2 * PLANE_BYTES)
#define FB1L (FB1H + 8192)
#define FB2H (FB1L + 8192)
#define FB2L (FB2H + 8192)

__global__ __launch_bounds__(256, 1)
void fused_gateup(const __nv_bfloat16* __restrict__ xs,
                  const __nv_bfloat16* __restrict__ w1p,
                  const __nv_bfloat16* __restrict__ w3p,
                  __nv_bfloat16* __restrict__ hs)
{
    extern __shared__ char smem[];
    const int t    = threadIdx.x;
    const int lane = t & 31;
    const int wid  = t >> 5;
    const int wm   = wid & 3;
    const int wn   = wid >> 2;
    const int m0   = blockIdx.y * BM;
    const int n0   = blockIdx.x * 64;
    const uint32_t sb0 = smem_u32(smem);
    const int CT = HDIM >> 6;     // 32

    float accG[2][4][4], accU[2][4][4];
#pragma unroll
    for (int i = 0; i < 2; i++)
#pragma unroll
        for (int j = 0; j < 4; j++)
#pragma unroll
            for (int k = 0; k < 4; k++) { accG[i][j][k] = 0.f; accU[i][j][k] = 0.f; }

    int amask[2]; uint32_t aoffr[2];
#pragma unroll
    for (int mt = 0; mt < 2; mt++) {
        int ar = wm * 32 + mt * 16 + (lane & 15);
        aoffr[mt] = (uint32_t)ar * 128;
        amask[mt] = ar & 7;
    }
    const int alo = lane >> 4;
    const int gq  = lane >> 3;
    int bmask[2]; uint32_t boffr[2];
#pragma unroll
    for (int nq = 0; nq < 2; nq++) {
        int nr = wn * 32 + nq * 16 + (lane & 7) + ((gq & 2) << 2);
        boffr[nq] = (uint32_t)nr * 128;
        bmask[nq] = nr & 7;
    }
    const int blo = gq & 1;

    auto issue = [&](int cc, int stage) {
        int k0 = cc * BK;
        uint32_t sb = sb0 + stage * STAGE_BYTES;
        load_plane(xs,       HDIM, m0, k0, sb,               t);
        load_plane(xs + P_X, HDIM, m0, k0, sb + PLANE_BYTES, t);
        load_plane64(w1p,        HDIM, n0, k0, sb + FB1H, t);
        load_plane64(w1p + P_W1, HDIM, n0, k0, sb + FB1L, t);
        load_plane64(w3p,        HDIM, n0, k0, sb + FB2H, t);
        load_plane64(w3p + P_W1, HDIM, n0, k0, sb + FB2L, t);
    };

    issue(0, 0); CP_COMMIT();
    issue(1, 1); CP_COMMIT();

#pragma unroll 1
    for (int cc = 0; cc < CT; cc++) {
        CP_WAIT1();
        __syncthreads();

        const uint32_t sb = sb0 + (cc % STAGES) * STAGE_BYTES;
        const uint32_t sAh = sb, sAl = sb + PLANE_BYTES;

#pragma unroll
        for (int ks = 0; ks < 4; ks++) {
            const int ac = ks * 2 + alo;
            const int bc = ks * 2 + blo;
            uint32_t ah[2][4], al[2][4];
            uint32_t b1h[4][2], b1l[4][2], b2h[4][2], b2l[4][2];
            // batch 1: ah, b1h, b2h -> pass1 of G and U
#pragma unroll
            for (int mt = 0; mt < 2; mt++)
                ldsm_x4(ah[mt], sAh + aoffr[mt] + (uint32_t)((ac ^ amask[mt]) << 4));
#pragma unroll
            for (int nq = 0; nq < 2; nq++) {
                uint32_t bo = boffr[nq] + (uint32_t)((bc ^ bmask[nq]) << 4);
                uint32_t r[4];
                ldsm_x4(r, sb + FB1H + bo);
                b1h[nq * 2][0] = r[0]; b1h[nq * 2][1] = r[1];
                b1h[nq * 2 + 1][0] = r[2]; b1h[nq * 2 + 1][1] = r[3];
                ldsm_x4(r, sb + FB2H + bo);
                b2h[nq * 2][0] = r[0]; b2h[nq * 2][1] = r[1];
                b2h[nq * 2 + 1][0] = r[2]; b2h[nq * 2 + 1][1] = r[3];
            }
#pragma unroll
            for (int mt = 0; mt < 2; mt++)
#pragma unroll
                for (int nt = 0; nt < 4; nt++) mma_bf16(accG[mt][nt], ah[mt], b1h[nt]);
#pragma unroll
            for (int mt = 0; mt < 2; mt++)
#pragma unroll
                for (int nt = 0; nt < 4; nt++) mma_bf16(accU[mt][nt], ah[mt], b2h[nt]);
            // batch 2: b1l, b2l -> pass2
#pragma unroll
            for (int nq = 0; nq < 2; nq++) {
                uint32_t bo = boffr[nq] + (uint32_t)((bc ^ bmask[nq]) << 4);
                uint32_t r[4];
                ldsm_x4(r, sb + FB1L + bo);
                b1l[nq * 2][0] = r[0]; b1l[nq * 2][1] = r[1];
                b1l[nq * 2 + 1][0] = r[2]; b1l[nq * 2 + 1][1] = r[3];
                ldsm_x4(r, sb + FB2L + bo);
                b2l[nq * 2][0] = r[0]; b2l[nq * 2][1] = r[1];
                b2l[nq * 2 + 1][0] = r[2]; b2l[nq * 2 + 1][1] = r[3];
            }
#pragma unroll
            for (int mt = 0; mt < 2; mt++)
#pragma unroll
                for (int nt = 0; nt < 4; nt++) mma_bf16(accG[mt][nt], ah[mt], b1l[nt]);
#pragma unroll
            for (int mt = 0; mt < 2; mt++)
#pragma unroll
                for (int nt = 0; nt < 4; nt++) mma_bf16(accU[mt][nt], ah[mt], b2l[nt]);
            // batch 3: al -> pass3
#pragma unroll
            for (int mt = 0; mt < 2; mt++)
                ldsm_x4(al[mt], sAl + aoffr[mt] + (uint32_t)((ac ^ amask[mt]) << 4));
#pragma unroll
            for (int mt = 0; mt < 2; mt++)
#pragma unroll
                for (int nt = 0; nt < 4; nt++) mma_bf16(accG[mt][nt], al[mt], b1h[nt]);
#pragma unroll
            for (int mt = 0; mt < 2; mt++)
#pragma unroll
                for (int nt = 0; nt < 4; nt++) mma_bf16(accU[mt][nt], al[mt], b2h[nt]);
        }
        int nc = cc + STAGES - 1;
        if (nc < CT) issue(nc, nc % STAGES);
        CP_COMMIT();
    }

#pragma unroll
    for (int mt = 0; mt < 2; mt++) {
        int row = m0 + wm * 32 + mt * 16 + (lane >> 2);
#pragma unroll
        for (int nt = 0; nt < 4; nt++) {
            int col = n0 + wn * 32 + nt * 8 + (lane & 3) * 2;
            float h00 = siluf(accG[mt][nt][0]) * accU[mt][nt][0];
            float h01 = siluf(accG[mt][nt][1]) * accU[mt][nt][1];
            float h10 = siluf(accG[mt][nt][2]) * accU[mt][nt][2];
            float h11 = siluf(accG[mt][nt][3]) * accU[mt][nt][3];
            split_store(hs, P_H, IDIM, row,     col, h00, h01);
            split_store(hs, P_H, IDIM, row + 8, col, h10, h11);
        }
    }
}

// ---------------------------------------------------------------------------
__global__ void split_kernel(const float* __restrict__ src, int src_ld,
                             int cols, int dstK,
                             __nv_bfloat16* __restrict__ dst, long long plane)
{
    int k0 = (blockIdx.x * blockDim.x + threadIdx.x) * 4;
    if (k0 >= dstK) return;
    int row = blockIdx.y;
    const float* s = src + (size_t)row * src_ld;
    __nv_bfloat16 hi[4], lo[4];
#pragma unroll
    for (int j = 0; j < 4; j++) {
        int k = k0 + j;
        float v = (k < cols) ? s[k] : 0.f;
        hi[j] = __float2bfloat16(v);
        lo[j] = __float2bfloat16(v - __bfloat162float(hi[j]));
    }
    size_t off = (size_t)row * dstK + k0;
    *reinterpret_cast<__nv_bfloat162*>(dst + off)     = __halves2bfloat162(hi[0], hi[1]);
    *reinterpret_cast<__nv_bfloat162*>(dst + off + 2) = __halves2bfloat162(hi[2], hi[3]);
    *reinterpret_cast<__nv_bfloat162*>(dst + off + plane)     = __halves2bfloat162(lo[0], lo[1]);
    *reinterpret_cast<__nv_bfloat162*>(dst + off + plane + 2) = __halves2bfloat162(lo[2], lo[3]);
}

__global__ void tsplit_kernel(const float* __restrict__ src, int C, int rows,
                              __nv_bfloat16* __restrict__ dst, long long plane)
{
    __shared__ float sm[32][33];
    int c0 = blockIdx.x * 32, r0 = blockIdx.y * 32;
    int tx = threadIdx.x, ty = threadIdx.y;
    int r = r0 + ty;
    float v = (r < rows) ? src[(size_t)r * C + c0 + tx] : 0.f;
    sm[ty][tx] = v;
    __syncthreads();
    float w = sm[tx][ty];
    __nv_bfloat16 hi = __float2bfloat16(w);
    __nv_bfloat16 lo = __float2bfloat16(w - __bfloat162float(hi));
    size_t off = (size_t)(c0 + ty) * RPAD + r0 + tx;
    dst[off] = hi;
    dst[off + plane] = lo;
}

__global__ void logits_kernel(const float* __restrict__ x,
                              const float* __restrict__ gw,
                              float* __restrict__ out)
{
    int warp = (blockIdx.x * blockDim.x + threadIdx.x) >> 5;
    int lane = threadIdx.x & 31;
    if (warp >= NTOK) return;
    const float* xr = x + (size_t)warp * HDIM;
    float acc[8] = {0.f, 0.f, 0.f, 0.f, 0.f, 0.f, 0.f, 0.f};
    for (int k = lane; k < HDIM; k += 32) {
        float xv = xr[k];
#pragma unroll
        for (int e = 0; e < 8; e++) acc[e] += xv * gw[e * HDIM + k];
    }
#pragma unroll
    for (int e = 0; e < 8; e++) {
        float v = acc[e];
#pragma unroll
        for (int o = 16; o; o >>= 1) v += __shfl_xor_sync(0xFFFFFFFFu, v, o);
        if (lane == 0) out[(size_t)warp * 8 + e] = v;
    }
}

// ---------------------------------------------------------------------------
static inline void run_split(const float* src, int src_ld, int rows,
                             int cols, int dstK, __nv_bfloat16* dst)
{
    long long plane = (long long)rows * dstK;
    dim3 grid((unsigned)((dstK + 1023) / 1024), (unsigned)rows);
    split_kernel<<<grid, 256>>>(src, src_ld, cols, dstK, dst, plane);
}
static inline void run_tsplit(const float* src, int C, int rows, __nv_bfloat16* dst)
{
    long long plane = (long long)C * RPAD;
    dim3 grid((unsigned)(C / 32), RPAD / 32);
    tsplit_kernel<<<grid, dim3(32, 32)>>>(src, C, rows, dst, plane);
}

extern "C" void kernel_launch(void* const* d_in, const int* in_sizes, int n_in,
                              void* d_out, int out_size)
{
    const float* x  = (const float*)d_in[0];
    const float* gw = (const float*)d_in[1];
    const float* w1 = (const float*)d_in[2];
    const float* w2 = (const float*)d_in[3];
    const float* w3 = (const float*)d_in[4];
    const float* u1 = (const float*)d_in[5];
    const float* v1 = (const float*)d_in[6];
    const float* u2 = (const float*)d_in[7];
    const float* v2 = (const float*)d_in[8];
    const float* u3 = (const float*)d_in[9];
    const float* v3 = (const float*)d_in[10];

    float* out    = (float*)d_out;
    float* logits = out + (size_t)NTOK * HDIM;

    __nv_bfloat16 *xs, *u1s, *u3s, *u2s, *v1ts, *v3ts, *v2ts;
    __nv_bfloat16 *w1ps, *w3ps, *w2ps, *hs;
    cudaGetSymbolAddress((void**)&xs,   g_xs);
    cudaGetSymbolAddress((void**)&u1s,  g_u1s);
    cudaGetSymbolAddress((void**)&u3s,  g_u3s);
    cudaGetSymbolAddress((void**)&u2s,  g_u2s);
    cudaGetSymbolAddress((void**)&v1ts, g_v1ts);
    cudaGetSymbolAddress((void**)&v3ts, g_v3ts);
    cudaGetSymbolAddress((void**)&v2ts, g_v2ts);
    cudaGetSymbolAddress((void**)&w1ps, g_w1ps);
    cudaGetSymbolAddress((void**)&w3ps, g_w3ps);
    cudaGetSymbolAddress((void**)&w2ps, g_w2ps);
    cudaGetSymbolAddress((void**)&hs,   g_hs);

    cudaFuncSetAttribute(prep_kernel,  cudaFuncAttributeMaxDynamicSharedMemorySize, SMEM_TOTAL);
    cudaFuncSetAttribute(down_kernel,  cudaFuncAttributeMaxDynamicSharedMemorySize, SMEM_TOTAL);
    cudaFuncSetAttribute(fused_gateup, cudaFuncAttributeMaxDynamicSharedMemorySize, SMEM_TOTAL);

    // ---- splits / transposes ----------------------------------------------
    run_split(x,  HDIM, NTOK, HDIM, HDIM, xs);
    run_split(u1, RDIM, IDIM, RDIM, RPAD, u1s);
    run_split(u3, RDIM, IDIM, RDIM, RPAD, u3s);
    run_split(u2, RDIM, HDIM, RDIM, RPAD, u2s);
    run_tsplit(v1, HDIM, RDIM, v1ts);
    run_tsplit(v3, HDIM, RDIM, v3ts);
    run_tsplit(v2, IDIM, RDIM, v2ts);

    dim3 blk(256);

    // ---- weight folding (one launch, z selects which W') ------------------
    prep_kernel<<<dim3(IDIM / BM, HDIM / BN, 3), blk, SMEM_TOTAL>>>(
        u1s, u3s, u2s, v1ts, v3ts, v2ts, w1, w3, w2, w1ps, w3ps, w2ps);

    // ---- fused gate/up + silu -> h planes ---------------------------------
    fused_gateup<<<dim3(IDIM / 64, NTOK / BM), blk, SMEM_TOTAL>>>(
        xs, w1ps, w3ps, hs);

    // ---- out = h @ W2'^T --------------------------------------------------
    down_kernel<<<dim3(HDIM / BN, NTOK / BM), blk, SMEM_TOTAL>>>(hs, w2ps, out);

    // ---- router logits ----------------------------------------------------
    {
        int tpb = 256;
        unsigned nb = (unsigned)((NTOK * 32 + tpb - 1) / tpb);
        logits_kernel<<<nb, tpb>>>(x, gw, logits);
    }
}